// round 6
// baseline (speedup 1.0000x reference)
#include <cuda_runtime.h>
#include <cuda_bf16.h>
#include <math.h>
#include <stdint.h>

// Problem constants
#define DMODEL 1024
#define NHEAD  16
#define HD     64
#define BATCH  4
#define SEQ    2048
#define NTOK   (BATCH * SEQ)          // 8192
#define QKVROW (3 * DMODEL)           // 3072

// Scratch (device globals: allocation-guard safe)
__device__ float g_qkv[(size_t)NTOK * QKVROW];
// bf16 hi/lo operands
__device__ __nv_bfloat16 g_xh[(size_t)NTOK * DMODEL];
__device__ __nv_bfloat16 g_xl[(size_t)NTOK * DMODEL];
__device__ __nv_bfloat16 g_yh[(size_t)NTOK * DMODEL];
__device__ __nv_bfloat16 g_yl[(size_t)NTOK * DMODEL];
__device__ __nv_bfloat16 g_wah[(size_t)QKVROW * DMODEL];  // W_attn^T hi
__device__ __nv_bfloat16 g_wal[(size_t)QKVROW * DMODEL];  // W_attn^T lo
__device__ __nv_bfloat16 g_wph[(size_t)DMODEL * DMODEL];  // W_proj^T hi
__device__ __nv_bfloat16 g_wpl[(size_t)DMODEL * DMODEL];  // W_proj^T lo
__device__ __nv_bfloat16 g_qh[(size_t)NTOK * DMODEL];
__device__ __nv_bfloat16 g_ql[(size_t)NTOK * DMODEL];
__device__ __nv_bfloat16 g_kh[(size_t)NTOK * DMODEL];
__device__ __nv_bfloat16 g_kl[(size_t)NTOK * DMODEL];
__device__ __nv_bfloat16 g_vth[(size_t)BATCH * NHEAD * HD * SEQ]; // [b,h,d,T]
__device__ __nv_bfloat16 g_vtl[(size_t)BATCH * NHEAD * HD * SEQ];

// ---------------------------------------------------------------------------
// PTX helpers (sm_80-era: valid on non-'a' PTX target)
// ---------------------------------------------------------------------------
__device__ __forceinline__ uint32_t smem_u32(const void* p) {
    uint32_t a;
    asm("{ .reg .u64 t; cvta.to.shared.u64 t, %1; cvt.u32.u64 %0, t; }"
        : "=r"(a) : "l"(p));
    return a;
}

__device__ __forceinline__ void ldsm4(uint32_t* r, uint32_t addr) {
    asm volatile("ldmatrix.sync.aligned.m8n8.x4.shared.b16 {%0,%1,%2,%3}, [%4];"
        : "=r"(r[0]), "=r"(r[1]), "=r"(r[2]), "=r"(r[3]) : "r"(addr));
}

__device__ __forceinline__ void mma_bf16(float* c, const uint32_t* a,
                                         const uint32_t* b) {
    asm volatile(
        "mma.sync.aligned.m16n8k16.row.col.f32.bf16.bf16.f32 "
        "{%0,%1,%2,%3}, {%4,%5,%6,%7}, {%8,%9}, {%0,%1,%2,%3};"
        : "+f"(c[0]), "+f"(c[1]), "+f"(c[2]), "+f"(c[3])
        : "r"(a[0]), "r"(a[1]), "r"(a[2]), "r"(a[3]), "r"(b[0]), "r"(b[1]));
}

__device__ __forceinline__ void cp16(uint32_t dst, const void* src) {
    asm volatile("cp.async.cg.shared.global [%0], [%1], 16;"
        :: "r"(dst), "l"(src));
}
#define CP_COMMIT() asm volatile("cp.async.commit_group;" ::: "memory")
#define CP_WAIT1()  asm volatile("cp.async.wait_group 1;" ::: "memory")
#define CP_WAIT0()  asm volatile("cp.async.wait_group 0;" ::: "memory")

__device__ __forceinline__ uint32_t packbf(__nv_bfloat16 a, __nv_bfloat16 b) {
    __nv_bfloat162 t = __halves2bfloat162(a, b);
    return *(uint32_t*)&t;
}

__device__ __forceinline__ void split4(float4 v, uint2& hi, uint2& lo) {
    __nv_bfloat16 hx = __float2bfloat16_rn(v.x);
    __nv_bfloat16 hy = __float2bfloat16_rn(v.y);
    __nv_bfloat16 hz = __float2bfloat16_rn(v.z);
    __nv_bfloat16 hw = __float2bfloat16_rn(v.w);
    __nv_bfloat16 lx = __float2bfloat16_rn(v.x - __bfloat162float(hx));
    __nv_bfloat16 ly = __float2bfloat16_rn(v.y - __bfloat162float(hy));
    __nv_bfloat16 lz = __float2bfloat16_rn(v.z - __bfloat162float(hz));
    __nv_bfloat16 lw = __float2bfloat16_rn(v.w - __bfloat162float(hw));
    hi.x = packbf(hx, hy); hi.y = packbf(hz, hw);
    lo.x = packbf(lx, ly); lo.y = packbf(lz, lw);
}

__device__ __forceinline__ uint32_t ld32(const __nv_bfloat16* p) {
    return *(const uint32_t*)p;
}

// ---------------------------------------------------------------------------
// Prepass: elementwise split fp32 -> bf16 hi/lo (for x)
// ---------------------------------------------------------------------------
__global__ void __launch_bounds__(256) split_kernel(
    const float* __restrict__ A,
    __nv_bfloat16* __restrict__ Ah, __nv_bfloat16* __restrict__ Al)
{
    const size_t i4 = ((size_t)blockIdx.x * 256 + threadIdx.x) * 4;
    float4 v = *(const float4*)(A + i4);
    uint2 hi, lo;
    split4(v, hi, lo);
    *(uint2*)(Ah + i4) = hi;
    *(uint2*)(Al + i4) = lo;
}

// ---------------------------------------------------------------------------
// Prepass: fused transpose + split.  Wt[n][k] = W[k][n] as bf16 hi/lo.
// ---------------------------------------------------------------------------
__global__ void __launch_bounds__(256) transpose_split_kernel(
    const float* __restrict__ W,
    __nv_bfloat16* __restrict__ Wth, __nv_bfloat16* __restrict__ Wtl,
    int K, int N)
{
    __shared__ float t[32][33];
    const int tx = threadIdx.x;
    const int ty = threadIdx.y;
    const int n0 = blockIdx.x * 32;
    const int k0 = blockIdx.y * 32;
    #pragma unroll
    for (int j = 0; j < 32; j += 8)
        t[ty + j][tx] = W[(size_t)(k0 + ty + j) * N + n0 + tx];
    __syncthreads();
    #pragma unroll
    for (int j = 0; j < 32; j += 8) {
        const float v = t[tx][ty + j];
        __nv_bfloat16 hi = __float2bfloat16_rn(v);
        __nv_bfloat16 lo = __float2bfloat16_rn(v - __bfloat162float(hi));
        const size_t o = (size_t)(n0 + ty + j) * K + k0 + tx;
        Wth[o] = hi;
        Wtl[o] = lo;
    }
}

// ---------------------------------------------------------------------------
// bf16 GEMM: C[M,N] = (Ah+Al)[M,K] @ (Bh+Bl)[N,K]^T  (3-term, fp32 accum)
// 128x128 CTA tile, BK=32, 8 warps (2m x 4n), warp tile 64x32.
// cp.async double buffered. SMEM row = 32 bf16 = 64B padded to 80B.
// Regions per buffer: Ah, Al, Bh, Bl : 128*80 = 10240B -> 40960B/buffer.
// ---------------------------------------------------------------------------
#define GSTR     80
#define GREG     (128 * GSTR)     // 10240
#define GBUF     (4 * GREG)       // 40960
#define SMEM_DYN (2 * GBUF)       // 81920

__global__ void __launch_bounds__(256) tc_gemm_bf16(
    const __nv_bfloat16* __restrict__ Ah, const __nv_bfloat16* __restrict__ Al,
    const __nv_bfloat16* __restrict__ Bh, const __nv_bfloat16* __restrict__ Bl,
    float* __restrict__ C, int M, int N, int K)
{
    extern __shared__ __align__(16) char dsm[];

    const int tid = threadIdx.x;
    const int wid = tid >> 5;
    const int lid = tid & 31;
    const int m0 = blockIdx.y * 128;
    const int n0 = blockIdx.x * 128;

    const int Wm = (wid >> 2) * 64;
    const int Wn = (wid & 3) * 32;

    const uint32_t sb = smem_u32(dsm);

    const int l16 = lid & 15;
    const int kh  = lid >> 4;
    const int bl8 = lid & 7;
    const int bkh = (lid >> 3) & 1;
    const int bnh = lid >> 4;

    // loader: thread -> 8 chunks of 16B. row = (p&1)*64 + tid/4, chunk = tid&3
    const int lrow = tid >> 2;          // 0..63
    const int lch  = tid & 3;           // 0..3 (16B chunks)

    auto load_tile = [&](uint32_t buf, int k0) {
        #pragma unroll
        for (int p = 0; p < 8; p++) {
            const int region = p >> 1;
            const int row = ((p & 1) << 6) + lrow;
            const uint32_t dst = buf + region * GREG + row * GSTR + lch * 16;
            const __nv_bfloat16* src;
            if (region == 0)
                src = Ah + (size_t)(m0 + row) * K + k0 + lch * 8;
            else if (region == 1)
                src = Al + (size_t)(m0 + row) * K + k0 + lch * 8;
            else if (region == 2)
                src = Bh + (size_t)(n0 + row) * K + k0 + lch * 8;
            else
                src = Bl + (size_t)(n0 + row) * K + k0 + lch * 8;
            cp16(dst, src);
        }
        CP_COMMIT();
    };

    float acc[4][4][4];
    #pragma unroll
    for (int i = 0; i < 4; i++)
        #pragma unroll
        for (int j = 0; j < 4; j++)
            #pragma unroll
            for (int c = 0; c < 4; c++) acc[i][j][c] = 0.0f;

    const int NIT = K >> 5;
    load_tile(sb, 0);
    if (NIT > 1) load_tile(sb + GBUF, 32);

    for (int it = 0; it < NIT; it++) {
        if (it + 1 < NIT) { CP_WAIT1(); } else { CP_WAIT0(); }
        __syncthreads();

        const uint32_t buf = sb + (uint32_t)(it & 1) * GBUF;
        #pragma unroll
        for (int ks = 0; ks < 2; ks++) {
            const uint32_t akoff = (uint32_t)(ks * 16 + kh * 8) * 2;
            const uint32_t bkoff = (uint32_t)(ks * 16 + bkh * 8) * 2;

            uint32_t ah[4][4], al[4][4];
            #pragma unroll
            for (int mt = 0; mt < 4; mt++) {
                const uint32_t row = (uint32_t)(Wm + mt * 16 + l16) * GSTR + akoff;
                ldsm4(ah[mt], buf + 0 * GREG + row);
                ldsm4(al[mt], buf + 1 * GREG + row);
            }
            uint32_t bh[2][4], bl[2][4];
            #pragma unroll
            for (int ng = 0; ng < 2; ng++) {
                const uint32_t row =
                    (uint32_t)(Wn + ng * 16 + bl8 + bnh * 8) * GSTR + bkoff;
                ldsm4(bh[ng], buf + 2 * GREG + row);
                ldsm4(bl[ng], buf + 3 * GREG + row);
            }

            #pragma unroll
            for (int mt = 0; mt < 4; mt++)
                #pragma unroll
                for (int ng = 0; ng < 2; ng++)
                    #pragma unroll
                    for (int hf = 0; hf < 2; hf++) {
                        float* c = acc[mt][ng * 2 + hf];
                        const uint32_t b1[2] = { bh[ng][hf * 2], bh[ng][hf * 2 + 1] };
                        const uint32_t b2[2] = { bl[ng][hf * 2], bl[ng][hf * 2 + 1] };
                        mma_bf16(c, ah[mt], b1);
                        mma_bf16(c, ah[mt], b2);
                        mma_bf16(c, al[mt], b1);
                    }
        }
        __syncthreads();
        if (it + 2 < NIT) load_tile(buf, (it + 2) * 32);
    }

    const int g  = lid >> 2;
    const int tg = (lid & 3) * 2;
    #pragma unroll
    for (int mt = 0; mt < 4; mt++) {
        #pragma unroll
        for (int nt = 0; nt < 4; nt++) {
            const int mrow = m0 + Wm + mt * 16 + g;
            const int ncol = n0 + Wn + nt * 8 + tg;
            float2 v0 = make_float2(acc[mt][nt][0], acc[mt][nt][1]);
            float2 v1 = make_float2(acc[mt][nt][2], acc[mt][nt][3]);
            *(float2*)(C + (size_t)mrow * N + ncol)       = v0;
            *(float2*)(C + (size_t)(mrow + 8) * N + ncol) = v1;
        }
    }
}

// ---------------------------------------------------------------------------
// Prepass: split Q (scaled) / K into bf16 hi/lo.
// ---------------------------------------------------------------------------
#define QSCALE (0.125f * 1.44269504088896f)

__global__ void __launch_bounds__(256) qk_split_kernel(
    const float* __restrict__ qkv,
    __nv_bfloat16* __restrict__ qhp, __nv_bfloat16* __restrict__ qlp,
    __nv_bfloat16* __restrict__ khp, __nv_bfloat16* __restrict__ klp)
{
    const int idx = blockIdx.x * 256 + threadIdx.x;
    const int tok = idx >> 9;
    const int c4  = (idx & 511) * 4;
    float4 v = *(const float4*)(qkv + (size_t)tok * QKVROW + c4);
    uint2 hi, lo;
    if (c4 < DMODEL) {
        v.x *= QSCALE; v.y *= QSCALE; v.z *= QSCALE; v.w *= QSCALE;
        split4(v, hi, lo);
        *(uint2*)(qhp + (size_t)tok * DMODEL + c4) = hi;
        *(uint2*)(qlp + (size_t)tok * DMODEL + c4) = lo;
    } else {
        split4(v, hi, lo);
        *(uint2*)(khp + (size_t)tok * DMODEL + c4 - DMODEL) = hi;
        *(uint2*)(klp + (size_t)tok * DMODEL + c4 - DMODEL) = lo;
    }
}

// ---------------------------------------------------------------------------
// Prepass: V -> transposed [b,h,d,T] bf16 hi/lo.
// ---------------------------------------------------------------------------
__global__ void __launch_bounds__(256) v_split_T_kernel(
    const float* __restrict__ qkv,
    __nv_bfloat16* __restrict__ vthp, __nv_bfloat16* __restrict__ vtlp)
{
    __shared__ float t[32][33];
    const int tx = threadIdx.x;
    const int ty = threadIdx.y;
    const int bh = blockIdx.z;
    const int b  = bh >> 4;
    const int h  = bh & 15;
    const int d0 = blockIdx.y * 32;
    const int t0 = blockIdx.x * 32;

    const size_t col = 2 * DMODEL + h * HD + d0 + tx;
    #pragma unroll
    for (int j = 0; j < 32; j += 8)
        t[ty + j][tx] = qkv[(size_t)(b * SEQ + t0 + ty + j) * QKVROW + col];
    __syncthreads();
    #pragma unroll
    for (int j = 0; j < 32; j += 8) {
        const float v = t[tx][ty + j];
        __nv_bfloat16 hi = __float2bfloat16_rn(v);
        __nv_bfloat16 lo = __float2bfloat16_rn(v - __bfloat162float(hi));
        const size_t o = (size_t)(bh * HD + d0 + ty + j) * SEQ + t0 + tx;
        vthp[o] = hi;
        vtlp[o] = lo;
    }
}

// ---------------------------------------------------------------------------
// Flash attention via mma.sync bf16 3-term split (from R4).
// Epilogue writes y as bf16 hi/lo (feeds proj GEMM directly).
// ---------------------------------------------------------------------------
#define KSTR    144
#define REGION  (64 * KSTR)
#define ABUF    (4 * REGION)
#define ATT_SMEM (2 * ABUF)

__global__ void __launch_bounds__(256) attn_mma_kernel(
    const __nv_bfloat16* __restrict__ qh, const __nv_bfloat16* __restrict__ ql,
    const __nv_bfloat16* __restrict__ kh, const __nv_bfloat16* __restrict__ kl,
    const __nv_bfloat16* __restrict__ vth, const __nv_bfloat16* __restrict__ vtl,
    __nv_bfloat16* __restrict__ yh, __nv_bfloat16* __restrict__ yl)
{
    extern __shared__ __align__(16) char asm_[];

    const int tid = threadIdx.x;
    const int wid = tid >> 5;
    const int lid = tid & 31;
    const int qt = gridDim.x - 1 - blockIdx.x;
    const int h  = blockIdx.y;
    const int b  = blockIdx.z;
    const int q0 = qt * 128;
    const int NT = 2 * (qt + 1);

    const uint32_t sb = smem_u32(asm_);

    const int g  = lid >> 2;
    const int c2 = (lid & 3) * 2;
    const int bl8 = lid & 7;
    const int bkh = (lid >> 3) & 1;
    const int bnh = lid >> 4;

    uint32_t aqh[4][4], aql[4][4];
    {
        const size_t r0 = (size_t)(b * SEQ + q0 + wid * 16 + g) * DMODEL + h * HD;
        const size_t r1 = r0 + 8 * DMODEL;
        #pragma unroll
        for (int ks = 0; ks < 4; ks++) {
            const int k0 = ks * 16 + c2;
            aqh[ks][0] = ld32(qh + r0 + k0);
            aqh[ks][1] = ld32(qh + r1 + k0);
            aqh[ks][2] = ld32(qh + r0 + k0 + 8);
            aqh[ks][3] = ld32(qh + r1 + k0 + 8);
            aql[ks][0] = ld32(ql + r0 + k0);
            aql[ks][1] = ld32(ql + r1 + k0);
            aql[ks][2] = ld32(ql + r0 + k0 + 8);
            aql[ks][3] = ld32(ql + r1 + k0 + 8);
        }
    }

    const size_t kbase = (size_t)(b * SEQ) * DMODEL + h * HD;
    const size_t vbase = (size_t)((b * NHEAD + h) * HD) * SEQ;

    auto load_tile = [&](uint32_t buf, int kt) {
        const int ch = tid & 7;
        const int rr = tid >> 3;
        #pragma unroll
        for (int p = 0; p < 8; p++) {
            const int region = p >> 1;
            const int row = ((p & 1) << 5) + rr;
            const uint32_t dst = buf + region * REGION + row * KSTR + ch * 16;
            const __nv_bfloat16* src;
            if (region == 0)
                src = kh + kbase + (size_t)(kt * 64 + row) * DMODEL + ch * 8;
            else if (region == 1)
                src = kl + kbase + (size_t)(kt * 64 + row) * DMODEL + ch * 8;
            else if (region == 2)
                src = vth + vbase + (size_t)row * SEQ + kt * 64 + ch * 8;
            else
                src = vtl + vbase + (size_t)row * SEQ + kt * 64 + ch * 8;
            cp16(dst, src);
        }
        CP_COMMIT();
    };

    float O[8][4];
    #pragma unroll
    for (int nt = 0; nt < 8; nt++)
        #pragma unroll
        for (int c = 0; c < 4; c++) O[nt][c] = 0.0f;
    float m0 = -INFINITY, m1 = -INFINITY, l0 = 0.0f, l1 = 0.0f;

    load_tile(sb, 0);
    if (NT > 1) load_tile(sb + ABUF, 1);

    for (int kt = 0; kt < NT; kt++) {
        if (kt + 1 < NT) { CP_WAIT1(); } else { CP_WAIT0(); }
        __syncthreads();

        const uint32_t buf = sb + (uint32_t)(kt & 1) * ABUF;

        float S[8][4];
        #pragma unroll
        for (int nt = 0; nt < 8; nt++)
            #pragma unroll
            for (int c = 0; c < 4; c++) S[nt][c] = 0.0f;

        #pragma unroll
        for (int ks = 0; ks < 4; ks++) {
            const uint32_t koff = (uint32_t)(ks * 16 + bkh * 8) * 2;
            #pragma unroll
            for (int ng = 0; ng < 4; ng++) {
                const uint32_t row = (uint32_t)(ng * 16 + bl8 + bnh * 8) * KSTR + koff;
                uint32_t kbh[4], kbl[4];
                ldsm4(kbh, buf + 0 * REGION + row);
                ldsm4(kbl, buf + 1 * REGION + row);
                #pragma unroll
                for (int hf = 0; hf < 2; hf++) {
                    float* c = S[ng * 2 + hf];
                    const uint32_t b1[2] = { kbh[hf * 2], kbh[hf * 2 + 1] };
                    const uint32_t b2[2] = { kbl[hf * 2], kbl[hf * 2 + 1] };
                    mma_bf16(c, aqh[ks], b1);
                    mma_bf16(c, aqh[ks], b2);
                    mma_bf16(c, aql[ks], b1);
                }
            }
        }

        if (kt >= 2 * qt) {
            const int qr0 = q0 + wid * 16 + g;
            #pragma unroll
            for (int nt = 0; nt < 8; nt++) {
                #pragma unroll
                for (int e = 0; e < 2; e++) {
                    const int key = kt * 64 + nt * 8 + c2 + e;
                    if (key > qr0)     S[nt][e]     = -INFINITY;
                    if (key > qr0 + 8) S[nt][2 + e] = -INFINITY;
                }
            }
        }

        float mx0 = -INFINITY, mx1 = -INFINITY;
        #pragma unroll
        for (int nt = 0; nt < 8; nt++) {
            mx0 = fmaxf(mx0, fmaxf(S[nt][0], S[nt][1]));
            mx1 = fmaxf(mx1, fmaxf(S[nt][2], S[nt][3]));
        }
        #pragma unroll
        for (int off = 1; off <= 2; off <<= 1) {
            mx0 = fmaxf(mx0, __shfl_xor_sync(0xffffffffu, mx0, off));
            mx1 = fmaxf(mx1, __shfl_xor_sync(0xffffffffu, mx1, off));
        }
        const float mn0 = fmaxf(m0, mx0);
        const float mn1 = fmaxf(m1, mx1);
        const float a0 = exp2f(m0 - mn0);
        const float a1 = exp2f(m1 - mn1);
        m0 = mn0; m1 = mn1;

        float rs0 = 0.0f, rs1 = 0.0f;
        #pragma unroll
        for (int nt = 0; nt < 8; nt++) {
            S[nt][0] = exp2f(S[nt][0] - m0);
            S[nt][1] = exp2f(S[nt][1] - m0);
            S[nt][2] = exp2f(S[nt][2] - m1);
            S[nt][3] = exp2f(S[nt][3] - m1);
            rs0 += S[nt][0] + S[nt][1];
            rs1 += S[nt][2] + S[nt][3];
        }
        #pragma unroll
        for (int off = 1; off <= 2; off <<= 1) {
            rs0 += __shfl_xor_sync(0xffffffffu, rs0, off);
            rs1 += __shfl_xor_sync(0xffffffffu, rs1, off);
        }
        l0 = l0 * a0 + rs0;
        l1 = l1 * a1 + rs1;

        #pragma unroll
        for (int nt = 0; nt < 8; nt++) {
            O[nt][0] *= a0; O[nt][1] *= a0;
            O[nt][2] *= a1; O[nt][3] *= a1;
        }

        uint32_t ph[4][4], pl[4][4];
        #pragma unroll
        for (int ks = 0; ks < 4; ks++) {
            #pragma unroll
            for (int r = 0; r < 4; r++) {
                const int nt = ks * 2 + (r >> 1);
                const float p0 = S[nt][(r & 1) * 2 + 0];
                const float p1 = S[nt][(r & 1) * 2 + 1];
                __nv_bfloat16 h0 = __float2bfloat16_rn(p0);
                __nv_bfloat16 h1 = __float2bfloat16_rn(p1);
                __nv_bfloat16 e0 = __float2bfloat16_rn(p0 - __bfloat162float(h0));
                __nv_bfloat16 e1 = __float2bfloat16_rn(p1 - __bfloat162float(h1));
                ph[ks][r] = packbf(h0, h1);
                pl[ks][r] = packbf(e0, e1);
            }
        }

        #pragma unroll
        for (int ks = 0; ks < 4; ks++) {
            const uint32_t koff = (uint32_t)(ks * 16 + bkh * 8) * 2;
            #pragma unroll
            for (int ng = 0; ng < 4; ng++) {
                const uint32_t row = (uint32_t)(ng * 16 + bl8 + bnh * 8) * KSTR + koff;
                uint32_t vbh[4], vbl[4];
                ldsm4(vbh, buf + 2 * REGION + row);
                ldsm4(vbl, buf + 3 * REGION + row);
                #pragma unroll
                for (int hf = 0; hf < 2; hf++) {
                    float* c = O[ng * 2 + hf];
                    const uint32_t b1[2] = { vbh[hf * 2], vbh[hf * 2 + 1] };
                    const uint32_t b2[2] = { vbl[hf * 2], vbl[hf * 2 + 1] };
                    mma_bf16(c, ph[ks], b1);
                    mma_bf16(c, ph[ks], b2);
                    mma_bf16(c, pl[ks], b1);
                }
            }
        }

        __syncthreads();
        if (kt + 2 < NT) load_tile(buf, kt + 2);
    }

    // normalize + store y as bf16 hi/lo
    const float inv0 = 1.0f / l0;
    const float inv1 = 1.0f / l1;
    const size_t o0 = (size_t)(b * SEQ + q0 + wid * 16 + g) * DMODEL + h * HD;
    const size_t o1 = o0 + 8 * DMODEL;
    #pragma unroll
    for (int nt = 0; nt < 8; nt++) {
        const float v00 = O[nt][0] * inv0, v01 = O[nt][1] * inv0;
        const float v10 = O[nt][2] * inv1, v11 = O[nt][3] * inv1;
        __nv_bfloat16 h00 = __float2bfloat16_rn(v00);
        __nv_bfloat16 h01 = __float2bfloat16_rn(v01);
        __nv_bfloat16 h10 = __float2bfloat16_rn(v10);
        __nv_bfloat16 h11 = __float2bfloat16_rn(v11);
        *(uint32_t*)(yh + o0 + nt * 8 + c2) = packbf(h00, h01);
        *(uint32_t*)(yh + o1 + nt * 8 + c2) = packbf(h10, h11);
        *(uint32_t*)(yl + o0 + nt * 8 + c2) = packbf(
            __float2bfloat16_rn(v00 - __bfloat162float(h00)),
            __float2bfloat16_rn(v01 - __bfloat162float(h01)));
        *(uint32_t*)(yl + o1 + nt * 8 + c2) = packbf(
            __float2bfloat16_rn(v10 - __bfloat162float(h10)),
            __float2bfloat16_rn(v11 - __bfloat162float(h11)));
    }
}

// ---------------------------------------------------------------------------
// Launch
// ---------------------------------------------------------------------------
extern "C" void kernel_launch(void* const* d_in, const int* in_sizes, int n_in,
                              void* d_out, int out_size)
{
    const float* x      = (const float*)d_in[0];
    const float* W_attn = (const float*)d_in[1];
    const float* W_proj = (const float*)d_in[2];
    float* out = (float*)d_out;

    void *p_qkv, *p_xh, *p_xl, *p_yh, *p_yl, *p_wah, *p_wal, *p_wph, *p_wpl;
    void *p_qh, *p_ql, *p_kh, *p_kl, *p_vh, *p_vl;
    cudaGetSymbolAddress(&p_qkv, g_qkv);
    cudaGetSymbolAddress(&p_xh, g_xh);
    cudaGetSymbolAddress(&p_xl, g_xl);
    cudaGetSymbolAddress(&p_yh, g_yh);
    cudaGetSymbolAddress(&p_yl, g_yl);
    cudaGetSymbolAddress(&p_wah, g_wah);
    cudaGetSymbolAddress(&p_wal, g_wal);
    cudaGetSymbolAddress(&p_wph, g_wph);
    cudaGetSymbolAddress(&p_wpl, g_wpl);
    cudaGetSymbolAddress(&p_qh, g_qh);
    cudaGetSymbolAddress(&p_ql, g_ql);
    cudaGetSymbolAddress(&p_kh, g_kh);
    cudaGetSymbolAddress(&p_kl, g_kl);
    cudaGetSymbolAddress(&p_vh, g_vth);
    cudaGetSymbolAddress(&p_vl, g_vtl);
    float* qkv = (float*)p_qkv;
    __nv_bfloat16* xh = (__nv_bfloat16*)p_xh;
    __nv_bfloat16* xl = (__nv_bfloat16*)p_xl;
    __nv_bfloat16* yh = (__nv_bfloat16*)p_yh;
    __nv_bfloat16* yl = (__nv_bfloat16*)p_yl;
    __nv_bfloat16* wah = (__nv_bfloat16*)p_wah;
    __nv_bfloat16* wal = (__nv_bfloat16*)p_wal;
    __nv_bfloat16* wph = (__nv_bfloat16*)p_wph;
    __nv_bfloat16* wpl = (__nv_bfloat16*)p_wpl;
    __nv_bfloat16* qh = (__nv_bfloat16*)p_qh;
    __nv_bfloat16* ql = (__nv_bfloat16*)p_ql;
    __nv_bfloat16* kh = (__nv_bfloat16*)p_kh;
    __nv_bfloat16* kl = (__nv_bfloat16*)p_kl;
    __nv_bfloat16* vth = (__nv_bfloat16*)p_vh;
    __nv_bfloat16* vtl = (__nv_bfloat16*)p_vl;

    cudaFuncSetAttribute(tc_gemm_bf16,
                         cudaFuncAttributeMaxDynamicSharedMemorySize, SMEM_DYN);
    cudaFuncSetAttribute(attn_mma_kernel,
                         cudaFuncAttributeMaxDynamicSharedMemorySize, ATT_SMEM);

    // 0) prepasses: split x, transpose+split weights
    split_kernel<<<(NTOK * DMODEL / 4) / 256, 256>>>(x, xh, xl);
    {
        dim3 blk(32, 8);
        transpose_split_kernel<<<dim3(QKVROW / 32, DMODEL / 32), blk>>>(
            W_attn, wah, wal, DMODEL, QKVROW);
        transpose_split_kernel<<<dim3(DMODEL / 32, DMODEL / 32), blk>>>(
            W_proj, wph, wpl, DMODEL, DMODEL);
    }

    // 1) qkv = x @ W_attn
    {
        dim3 grid(QKVROW / 128, NTOK / 128);
        tc_gemm_bf16<<<grid, 256, SMEM_DYN>>>(xh, xl, wah, wal, qkv,
                                              NTOK, QKVROW, DMODEL);
    }

    // 2) prepass: split q/k, split+transpose v
    qk_split_kernel<<<(NTOK * 2048 / 4) / 256, 256>>>(qkv, qh, ql, kh, kl);
    {
        dim3 blk(32, 8);
        v_split_T_kernel<<<dim3(SEQ / 32, HD / 32, BATCH * NHEAD), blk>>>(qkv, vth, vtl);
    }

    // 3) attention -> y (bf16 hi/lo)
    {
        dim3 grid(SEQ / 128, NHEAD, BATCH);
        attn_mma_kernel<<<grid, 256, ATT_SMEM>>>(qh, ql, kh, kl, vth, vtl, yh, yl);
    }

    // 4) out = y @ W_proj
    {
        dim3 grid(DMODEL / 128, NTOK / 128);
        tc_gemm_bf16<<<grid, 256, SMEM_DYN>>>(yh, yl, wph, wpl, out,
                                              NTOK, DMODEL, DMODEL);
    }
}

// round 11
// speedup vs baseline: 1.7199x; 1.7199x over previous
#include <cuda_runtime.h>
#include <cuda_bf16.h>
#include <math.h>
#include <stdint.h>

// Problem constants
#define DMODEL 1024
#define NHEAD  16
#define HD     64
#define BATCH  4
#define SEQ    2048
#define NTOK   (BATCH * SEQ)          // 8192
#define QKVROW (3 * DMODEL)           // 3072

// Scratch (device globals: allocation-guard safe)
__device__ float g_qkv[(size_t)NTOK * QKVROW];
__device__ __nv_bfloat16 g_xh[(size_t)NTOK * DMODEL];
__device__ __nv_bfloat16 g_xl[(size_t)NTOK * DMODEL];
__device__ __nv_bfloat16 g_yh[(size_t)NTOK * DMODEL];
__device__ __nv_bfloat16 g_yl[(size_t)NTOK * DMODEL];
__device__ __nv_bfloat16 g_wah[(size_t)QKVROW * DMODEL];
__device__ __nv_bfloat16 g_wal[(size_t)QKVROW * DMODEL];
__device__ __nv_bfloat16 g_wph[(size_t)DMODEL * DMODEL];
__device__ __nv_bfloat16 g_wpl[(size_t)DMODEL * DMODEL];
__device__ __nv_bfloat16 g_qh[(size_t)NTOK * DMODEL];
__device__ __nv_bfloat16 g_ql[(size_t)NTOK * DMODEL];
__device__ __nv_bfloat16 g_kh[(size_t)NTOK * DMODEL];
__device__ __nv_bfloat16 g_kl[(size_t)NTOK * DMODEL];
__device__ __nv_bfloat16 g_vth[(size_t)BATCH * NHEAD * HD * SEQ]; // [b,h,d,T]
__device__ __nv_bfloat16 g_vtl[(size_t)BATCH * NHEAD * HD * SEQ];

// ---------------------------------------------------------------------------
// PTX helpers
// ---------------------------------------------------------------------------
__device__ __forceinline__ uint32_t smem_u32(const void* p) {
    uint32_t a;
    asm("{ .reg .u64 t; cvta.to.shared.u64 t, %1; cvt.u32.u64 %0, t; }"
        : "=r"(a) : "l"(p));
    return a;
}

__device__ __forceinline__ void ldsm4(uint32_t* r, uint32_t addr) {
    asm volatile("ldmatrix.sync.aligned.m8n8.x4.shared.b16 {%0,%1,%2,%3}, [%4];"
        : "=r"(r[0]), "=r"(r[1]), "=r"(r[2]), "=r"(r[3]) : "r"(addr));
}

__device__ __forceinline__ void mma_bf16(float* c, const uint32_t* a,
                                         const uint32_t* b) {
    asm volatile(
        "mma.sync.aligned.m16n8k16.row.col.f32.bf16.bf16.f32 "
        "{%0,%1,%2,%3}, {%4,%5,%6,%7}, {%8,%9}, {%0,%1,%2,%3};"
        : "+f"(c[0]), "+f"(c[1]), "+f"(c[2]), "+f"(c[3])
        : "r"(a[0]), "r"(a[1]), "r"(a[2]), "r"(a[3]), "r"(b[0]), "r"(b[1]));
}

__device__ __forceinline__ void cp16(uint32_t dst, const void* src) {
    asm volatile("cp.async.cg.shared.global [%0], [%1], 16;"
        :: "r"(dst), "l"(src));
}
#define CP_COMMIT() asm volatile("cp.async.commit_group;" ::: "memory")
#define CP_WAIT1()  asm volatile("cp.async.wait_group 1;" ::: "memory")
#define CP_WAIT0()  asm volatile("cp.async.wait_group 0;" ::: "memory")

__device__ __forceinline__ uint32_t packbf(__nv_bfloat16 a, __nv_bfloat16 b) {
    __nv_bfloat162 t = __halves2bfloat162(a, b);
    return *(uint32_t*)&t;
}

__device__ __forceinline__ void split4(float4 v, uint2& hi, uint2& lo) {
    __nv_bfloat16 hx = __float2bfloat16_rn(v.x);
    __nv_bfloat16 hy = __float2bfloat16_rn(v.y);
    __nv_bfloat16 hz = __float2bfloat16_rn(v.z);
    __nv_bfloat16 hw = __float2bfloat16_rn(v.w);
    __nv_bfloat16 lx = __float2bfloat16_rn(v.x - __bfloat162float(hx));
    __nv_bfloat16 ly = __float2bfloat16_rn(v.y - __bfloat162float(hy));
    __nv_bfloat16 lz = __float2bfloat16_rn(v.z - __bfloat162float(hz));
    __nv_bfloat16 lw = __float2bfloat16_rn(v.w - __bfloat162float(hw));
    hi.x = packbf(hx, hy); hi.y = packbf(hz, hw);
    lo.x = packbf(lx, ly); lo.y = packbf(lz, lw);
}

__device__ __forceinline__ uint32_t ld32(const __nv_bfloat16* p) {
    return *(const uint32_t*)p;
}

// ---------------------------------------------------------------------------
// Prepass: elementwise split fp32 -> bf16 hi/lo
// ---------------------------------------------------------------------------
__global__ void __launch_bounds__(256) split_kernel(
    const float* __restrict__ A,
    __nv_bfloat16* __restrict__ Ah, __nv_bfloat16* __restrict__ Al)
{
    const size_t i4 = ((size_t)blockIdx.x * 256 + threadIdx.x) * 4;
    float4 v = *(const float4*)(A + i4);
    uint2 hi, lo;
    split4(v, hi, lo);
    *(uint2*)(Ah + i4) = hi;
    *(uint2*)(Al + i4) = lo;
}

// ---------------------------------------------------------------------------
// Prepass: fused transpose + split.
// ---------------------------------------------------------------------------
__global__ void __launch_bounds__(256) transpose_split_kernel(
    const float* __restrict__ W,
    __nv_bfloat16* __restrict__ Wth, __nv_bfloat16* __restrict__ Wtl,
    int K, int N)
{
    __shared__ float t[32][33];
    const int tx = threadIdx.x;
    const int ty = threadIdx.y;
    const int n0 = blockIdx.x * 32;
    const int k0 = blockIdx.y * 32;
    #pragma unroll
    for (int j = 0; j < 32; j += 8)
        t[ty + j][tx] = W[(size_t)(k0 + ty + j) * N + n0 + tx];
    __syncthreads();
    #pragma unroll
    for (int j = 0; j < 32; j += 8) {
        const float v = t[tx][ty + j];
        __nv_bfloat16 hi = __float2bfloat16_rn(v);
        __nv_bfloat16 lo = __float2bfloat16_rn(v - __bfloat162float(hi));
        const size_t o = (size_t)(n0 + ty + j) * K + k0 + tx;
        Wth[o] = hi;
        Wtl[o] = lo;
    }
}

// ---------------------------------------------------------------------------
// bf16 GEMM (3-term), 128x128 tile, BK=32, cp.async double buffer.
// __launch_bounds__(256, 2): 2 CTAs/SM (regs<=128, 2x80KB smem).
// ---------------------------------------------------------------------------
#define GSTR     80
#define GREG     (128 * GSTR)
#define GBUF     (4 * GREG)       // 40960
#define SMEM_DYN (2 * GBUF)       // 81920

__global__ void __launch_bounds__(256, 2) tc_gemm_bf16(
    const __nv_bfloat16* __restrict__ Ah, const __nv_bfloat16* __restrict__ Al,
    const __nv_bfloat16* __restrict__ Bh, const __nv_bfloat16* __restrict__ Bl,
    float* __restrict__ C, int M, int N, int K)
{
    extern __shared__ __align__(16) char dsm[];

    const int tid = threadIdx.x;
    const int wid = tid >> 5;
    const int lid = tid & 31;
    const int m0 = blockIdx.y * 128;
    const int n0 = blockIdx.x * 128;

    const int Wm = (wid >> 2) * 64;
    const int Wn = (wid & 3) * 32;

    const uint32_t sb = smem_u32(dsm);

    const int l16 = lid & 15;
    const int kh  = lid >> 4;
    const int bl8 = lid & 7;
    const int bkh = (lid >> 3) & 1;
    const int bnh = lid >> 4;

    const int lrow = tid >> 2;          // 0..63
    const int lch  = tid & 3;           // 16B chunk

    auto load_tile = [&](uint32_t buf, int k0) {
        #pragma unroll
        for (int p = 0; p < 8; p++) {
            const int region = p >> 1;
            const int row = ((p & 1) << 6) + lrow;
            const uint32_t dst = buf + region * GREG + row * GSTR + lch * 16;
            const __nv_bfloat16* src;
            if (region == 0)
                src = Ah + (size_t)(m0 + row) * K + k0 + lch * 8;
            else if (region == 1)
                src = Al + (size_t)(m0 + row) * K + k0 + lch * 8;
            else if (region == 2)
                src = Bh + (size_t)(n0 + row) * K + k0 + lch * 8;
            else
                src = Bl + (size_t)(n0 + row) * K + k0 + lch * 8;
            cp16(dst, src);
        }
        CP_COMMIT();
    };

    float acc[4][4][4];
    #pragma unroll
    for (int i = 0; i < 4; i++)
        #pragma unroll
        for (int j = 0; j < 4; j++)
            #pragma unroll
            for (int c = 0; c < 4; c++) acc[i][j][c] = 0.0f;

    const int NIT = K >> 5;
    load_tile(sb, 0);
    if (NIT > 1) load_tile(sb + GBUF, 32);

    for (int it = 0; it < NIT; it++) {
        if (it + 1 < NIT) { CP_WAIT1(); } else { CP_WAIT0(); }
        __syncthreads();

        const uint32_t buf = sb + (uint32_t)(it & 1) * GBUF;
        #pragma unroll
        for (int ks = 0; ks < 2; ks++) {
            const uint32_t akoff = (uint32_t)(ks * 16 + kh * 8) * 2;
            const uint32_t bkoff = (uint32_t)(ks * 16 + bkh * 8) * 2;

            uint32_t ah[4][4], al[4][4];
            #pragma unroll
            for (int mt = 0; mt < 4; mt++) {
                const uint32_t row = (uint32_t)(Wm + mt * 16 + l16) * GSTR + akoff;
                ldsm4(ah[mt], buf + 0 * GREG + row);
                ldsm4(al[mt], buf + 1 * GREG + row);
            }
            uint32_t bh[2][4], bl[2][4];
            #pragma unroll
            for (int ng = 0; ng < 2; ng++) {
                const uint32_t row =
                    (uint32_t)(Wn + ng * 16 + bl8 + bnh * 8) * GSTR + bkoff;
                ldsm4(bh[ng], buf + 2 * GREG + row);
                ldsm4(bl[ng], buf + 3 * GREG + row);
            }

            // term-major: no accumulator sees back-to-back dependent mma
            #pragma unroll
            for (int term = 0; term < 3; term++) {
                #pragma unroll
                for (int mt = 0; mt < 4; mt++)
                    #pragma unroll
                    for (int ng = 0; ng < 2; ng++)
                        #pragma unroll
                        for (int hf = 0; hf < 2; hf++) {
                            float* c = acc[mt][ng * 2 + hf];
                            const uint32_t* af = (term == 2) ? al[mt] : ah[mt];
                            const uint32_t* bsrc = (term == 1) ? bl[ng] : bh[ng];
                            const uint32_t bf[2] = { bsrc[hf * 2], bsrc[hf * 2 + 1] };
                            mma_bf16(c, af, bf);
                        }
            }
        }
        __syncthreads();
        if (it + 2 < NIT) load_tile(buf, (it + 2) * 32);
    }

    const int g  = lid >> 2;
    const int tg = (lid & 3) * 2;
    #pragma unroll
    for (int mt = 0; mt < 4; mt++) {
        #pragma unroll
        for (int nt = 0; nt < 4; nt++) {
            const int mrow = m0 + Wm + mt * 16 + g;
            const int ncol = n0 + Wn + nt * 8 + tg;
            float2 v0 = make_float2(acc[mt][nt][0], acc[mt][nt][1]);
            float2 v1 = make_float2(acc[mt][nt][2], acc[mt][nt][3]);
            *(float2*)(C + (size_t)mrow * N + ncol)       = v0;
            *(float2*)(C + (size_t)(mrow + 8) * N + ncol) = v1;
        }
    }
}

// ---------------------------------------------------------------------------
// Prepass: split Q (scaled) / K into bf16 hi/lo.
// ---------------------------------------------------------------------------
#define QSCALE (0.125f * 1.44269504088896f)

__global__ void __launch_bounds__(256) qk_split_kernel(
    const float* __restrict__ qkv,
    __nv_bfloat16* __restrict__ qhp, __nv_bfloat16* __restrict__ qlp,
    __nv_bfloat16* __restrict__ khp, __nv_bfloat16* __restrict__ klp)
{
    const int idx = blockIdx.x * 256 + threadIdx.x;
    const int tok = idx >> 9;
    const int c4  = (idx & 511) * 4;
    float4 v = *(const float4*)(qkv + (size_t)tok * QKVROW + c4);
    uint2 hi, lo;
    if (c4 < DMODEL) {
        v.x *= QSCALE; v.y *= QSCALE; v.z *= QSCALE; v.w *= QSCALE;
        split4(v, hi, lo);
        *(uint2*)(qhp + (size_t)tok * DMODEL + c4) = hi;
        *(uint2*)(qlp + (size_t)tok * DMODEL + c4) = lo;
    } else {
        split4(v, hi, lo);
        *(uint2*)(khp + (size_t)tok * DMODEL + c4 - DMODEL) = hi;
        *(uint2*)(klp + (size_t)tok * DMODEL + c4 - DMODEL) = lo;
    }
}

// ---------------------------------------------------------------------------
// Prepass: V -> transposed [b,h,d,T] bf16 hi/lo.
// ---------------------------------------------------------------------------
__global__ void __launch_bounds__(256) v_split_T_kernel(
    const float* __restrict__ qkv,
    __nv_bfloat16* __restrict__ vthp, __nv_bfloat16* __restrict__ vtlp)
{
    __shared__ float t[32][33];
    const int tx = threadIdx.x;
    const int ty = threadIdx.y;
    const int bh = blockIdx.z;
    const int b  = bh >> 4;
    const int h  = bh & 15;
    const int d0 = blockIdx.y * 32;
    const int t0 = blockIdx.x * 32;

    const size_t col = 2 * DMODEL + h * HD + d0 + tx;
    #pragma unroll
    for (int j = 0; j < 32; j += 8)
        t[ty + j][tx] = qkv[(size_t)(b * SEQ + t0 + ty + j) * QKVROW + col];
    __syncthreads();
    #pragma unroll
    for (int j = 0; j < 32; j += 8) {
        const float v = t[tx][ty + j];
        __nv_bfloat16 hi = __float2bfloat16_rn(v);
        __nv_bfloat16 lo = __float2bfloat16_rn(v - __bfloat162float(hi));
        const size_t o = (size_t)(bh * HD + d0 + ty + j) * SEQ + t0 + tx;
        vthp[o] = hi;
        vtlp[o] = lo;
    }
}

// ---------------------------------------------------------------------------
// Flash attention via mma.sync bf16 3-term (unchanged from R5).
// ---------------------------------------------------------------------------
#define KSTR    144
#define REGION  (64 * KSTR)
#define ABUF    (4 * REGION)
#define ATT_SMEM (2 * ABUF)

__global__ void __launch_bounds__(256) attn_mma_kernel(
    const __nv_bfloat16* __restrict__ qh, const __nv_bfloat16* __restrict__ ql,
    const __nv_bfloat16* __restrict__ kh, const __nv_bfloat16* __restrict__ kl,
    const __nv_bfloat16* __restrict__ vth, const __nv_bfloat16* __restrict__ vtl,
    __nv_bfloat16* __restrict__ yh, __nv_bfloat16* __restrict__ yl)
{
    extern __shared__ __align__(16) char asm_[];

    const int tid = threadIdx.x;
    const int wid = tid >> 5;
    const int lid = tid & 31;
    const int qt = gridDim.x - 1 - blockIdx.x;
    const int h  = blockIdx.y;
    const int b  = blockIdx.z;
    const int q0 = qt * 128;
    const int NT = 2 * (qt + 1);

    const uint32_t sb = smem_u32(asm_);

    const int g  = lid >> 2;
    const int c2 = (lid & 3) * 2;
    const int bl8 = lid & 7;
    const int bkh = (lid >> 3) & 1;
    const int bnh = lid >> 4;

    uint32_t aqh[4][4], aql[4][4];
    {
        const size_t r0 = (size_t)(b * SEQ + q0 + wid * 16 + g) * DMODEL + h * HD;
        const size_t r1 = r0 + 8 * DMODEL;
        #pragma unroll
        for (int ks = 0; ks < 4; ks++) {
            const int k0 = ks * 16 + c2;
            aqh[ks][0] = ld32(qh + r0 + k0);
            aqh[ks][1] = ld32(qh + r1 + k0);
            aqh[ks][2] = ld32(qh + r0 + k0 + 8);
            aqh[ks][3] = ld32(qh + r1 + k0 + 8);
            aql[ks][0] = ld32(ql + r0 + k0);
            aql[ks][1] = ld32(ql + r1 + k0);
            aql[ks][2] = ld32(ql + r0 + k0 + 8);
            aql[ks][3] = ld32(ql + r1 + k0 + 8);
        }
    }

    const size_t kbase = (size_t)(b * SEQ) * DMODEL + h * HD;
    const size_t vbase = (size_t)((b * NHEAD + h) * HD) * SEQ;

    auto load_tile = [&](uint32_t buf, int kt) {
        const int ch = tid & 7;
        const int rr = tid >> 3;
        #pragma unroll
        for (int p = 0; p < 8; p++) {
            const int region = p >> 1;
            const int row = ((p & 1) << 5) + rr;
            const uint32_t dst = buf + region * REGION + row * KSTR + ch * 16;
            const __nv_bfloat16* src;
            if (region == 0)
                src = kh + kbase + (size_t)(kt * 64 + row) * DMODEL + ch * 8;
            else if (region == 1)
                src = kl + kbase + (size_t)(kt * 64 + row) * DMODEL + ch * 8;
            else if (region == 2)
                src = vth + vbase + (size_t)row * SEQ + kt * 64 + ch * 8;
            else
                src = vtl + vbase + (size_t)row * SEQ + kt * 64 + ch * 8;
            cp16(dst, src);
        }
        CP_COMMIT();
    };

    float O[8][4];
    #pragma unroll
    for (int nt = 0; nt < 8; nt++)
        #pragma unroll
        for (int c = 0; c < 4; c++) O[nt][c] = 0.0f;
    float m0 = -INFINITY, m1 = -INFINITY, l0 = 0.0f, l1 = 0.0f;

    load_tile(sb, 0);
    if (NT > 1) load_tile(sb + ABUF, 1);

    for (int kt = 0; kt < NT; kt++) {
        if (kt + 1 < NT) { CP_WAIT1(); } else { CP_WAIT0(); }
        __syncthreads();

        const uint32_t buf = sb + (uint32_t)(kt & 1) * ABUF;

        float S[8][4];
        #pragma unroll
        for (int nt = 0; nt < 8; nt++)
            #pragma unroll
            for (int c = 0; c < 4; c++) S[nt][c] = 0.0f;

        #pragma unroll
        for (int ks = 0; ks < 4; ks++) {
            const uint32_t koff = (uint32_t)(ks * 16 + bkh * 8) * 2;
            #pragma unroll
            for (int ng = 0; ng < 4; ng++) {
                const uint32_t row = (uint32_t)(ng * 16 + bl8 + bnh * 8) * KSTR + koff;
                uint32_t kbh[4], kbl[4];
                ldsm4(kbh, buf + 0 * REGION + row);
                ldsm4(kbl, buf + 1 * REGION + row);
                #pragma unroll
                for (int hf = 0; hf < 2; hf++) {
                    float* c = S[ng * 2 + hf];
                    const uint32_t b1[2] = { kbh[hf * 2], kbh[hf * 2 + 1] };
                    const uint32_t b2[2] = { kbl[hf * 2], kbl[hf * 2 + 1] };
                    mma_bf16(c, aqh[ks], b1);
                    mma_bf16(c, aqh[ks], b2);
                    mma_bf16(c, aql[ks], b1);
                }
            }
        }

        if (kt >= 2 * qt) {
            const int qr0 = q0 + wid * 16 + g;
            #pragma unroll
            for (int nt = 0; nt < 8; nt++) {
                #pragma unroll
                for (int e = 0; e < 2; e++) {
                    const int key = kt * 64 + nt * 8 + c2 + e;
                    if (key > qr0)     S[nt][e]     = -INFINITY;
                    if (key > qr0 + 8) S[nt][2 + e] = -INFINITY;
                }
            }
        }

        float mx0 = -INFINITY, mx1 = -INFINITY;
        #pragma unroll
        for (int nt = 0; nt < 8; nt++) {
            mx0 = fmaxf(mx0, fmaxf(S[nt][0], S[nt][1]));
            mx1 = fmaxf(mx1, fmaxf(S[nt][2], S[nt][3]));
        }
        #pragma unroll
        for (int off = 1; off <= 2; off <<= 1) {
            mx0 = fmaxf(mx0, __shfl_xor_sync(0xffffffffu, mx0, off));
            mx1 = fmaxf(mx1, __shfl_xor_sync(0xffffffffu, mx1, off));
        }
        const float mn0 = fmaxf(m0, mx0);
        const float mn1 = fmaxf(m1, mx1);
        const float a0 = exp2f(m0 - mn0);
        const float a1 = exp2f(m1 - mn1);
        m0 = mn0; m1 = mn1;

        float rs0 = 0.0f, rs1 = 0.0f;
        #pragma unroll
        for (int nt = 0; nt < 8; nt++) {
            S[nt][0] = exp2f(S[nt][0] - m0);
            S[nt][1] = exp2f(S[nt][1] - m0);
            S[nt][2] = exp2f(S[nt][2] - m1);
            S[nt][3] = exp2f(S[nt][3] - m1);
            rs0 += S[nt][0] + S[nt][1];
            rs1 += S[nt][2] + S[nt][3];
        }
        #pragma unroll
        for (int off = 1; off <= 2; off <<= 1) {
            rs0 += __shfl_xor_sync(0xffffffffu, rs0, off);
            rs1 += __shfl_xor_sync(0xffffffffu, rs1, off);
        }
        l0 = l0 * a0 + rs0;
        l1 = l1 * a1 + rs1;

        #pragma unroll
        for (int nt = 0; nt < 8; nt++) {
            O[nt][0] *= a0; O[nt][1] *= a0;
            O[nt][2] *= a1; O[nt][3] *= a1;
        }

        uint32_t ph[4][4], pl[4][4];
        #pragma unroll
        for (int ks = 0; ks < 4; ks++) {
            #pragma unroll
            for (int r = 0; r < 4; r++) {
                const int nt = ks * 2 + (r >> 1);
                const float p0 = S[nt][(r & 1) * 2 + 0];
                const float p1 = S[nt][(r & 1) * 2 + 1];
                __nv_bfloat16 h0 = __float2bfloat16_rn(p0);
                __nv_bfloat16 h1 = __float2bfloat16_rn(p1);
                __nv_bfloat16 e0 = __float2bfloat16_rn(p0 - __bfloat162float(h0));
                __nv_bfloat16 e1 = __float2bfloat16_rn(p1 - __bfloat162float(h1));
                ph[ks][r] = packbf(h0, h1);
                pl[ks][r] = packbf(e0, e1);
            }
        }

        #pragma unroll
        for (int ks = 0; ks < 4; ks++) {
            const uint32_t koff = (uint32_t)(ks * 16 + bkh * 8) * 2;
            #pragma unroll
            for (int ng = 0; ng < 4; ng++) {
                const uint32_t row = (uint32_t)(ng * 16 + bl8 + bnh * 8) * KSTR + koff;
                uint32_t vbh[4], vbl[4];
                ldsm4(vbh, buf + 2 * REGION + row);
                ldsm4(vbl, buf + 3 * REGION + row);
                #pragma unroll
                for (int hf = 0; hf < 2; hf++) {
                    float* c = O[ng * 2 + hf];
                    const uint32_t b1[2] = { vbh[hf * 2], vbh[hf * 2 + 1] };
                    const uint32_t b2[2] = { vbl[hf * 2], vbl[hf * 2 + 1] };
                    mma_bf16(c, ph[ks], b1);
                    mma_bf16(c, ph[ks], b2);
                    mma_bf16(c, pl[ks], b1);
                }
            }
        }

        __syncthreads();
        if (kt + 2 < NT) load_tile(buf, kt + 2);
    }

    const float inv0 = 1.0f / l0;
    const float inv1 = 1.0f / l1;
    const size_t o0 = (size_t)(b * SEQ + q0 + wid * 16 + g) * DMODEL + h * HD;
    const size_t o1 = o0 + 8 * DMODEL;
    #pragma unroll
    for (int nt = 0; nt < 8; nt++) {
        const float v00 = O[nt][0] * inv0, v01 = O[nt][1] * inv0;
        const float v10 = O[nt][2] * inv1, v11 = O[nt][3] * inv1;
        __nv_bfloat16 h00 = __float2bfloat16_rn(v00);
        __nv_bfloat16 h01 = __float2bfloat16_rn(v01);
        __nv_bfloat16 h10 = __float2bfloat16_rn(v10);
        __nv_bfloat16 h11 = __float2bfloat16_rn(v11);
        *(uint32_t*)(yh + o0 + nt * 8 + c2) = packbf(h00, h01);
        *(uint32_t*)(yh + o1 + nt * 8 + c2) = packbf(h10, h11);
        *(uint32_t*)(yl + o0 + nt * 8 + c2) = packbf(
            __float2bfloat16_rn(v00 - __bfloat162float(h00)),
            __float2bfloat16_rn(v01 - __bfloat162float(h01)));
        *(uint32_t*)(yl + o1 + nt * 8 + c2) = packbf(
            __float2bfloat16_rn(v10 - __bfloat162float(h10)),
            __float2bfloat16_rn(v11 - __bfloat162float(h11)));
    }
}

// ---------------------------------------------------------------------------
// Launch
// ---------------------------------------------------------------------------
extern "C" void kernel_launch(void* const* d_in, const int* in_sizes, int n_in,
                              void* d_out, int out_size)
{
    const float* x      = (const float*)d_in[0];
    const float* W_attn = (const float*)d_in[1];
    const float* W_proj = (const float*)d_in[2];
    float* out = (float*)d_out;

    void *p_qkv, *p_xh, *p_xl, *p_yh, *p_yl, *p_wah, *p_wal, *p_wph, *p_wpl;
    void *p_qh, *p_ql, *p_kh, *p_kl, *p_vh, *p_vl;
    cudaGetSymbolAddress(&p_qkv, g_qkv);
    cudaGetSymbolAddress(&p_xh, g_xh);
    cudaGetSymbolAddress(&p_xl, g_xl);
    cudaGetSymbolAddress(&p_yh, g_yh);
    cudaGetSymbolAddress(&p_yl, g_yl);
    cudaGetSymbolAddress(&p_wah, g_wah);
    cudaGetSymbolAddress(&p_wal, g_wal);
    cudaGetSymbolAddress(&p_wph, g_wph);
    cudaGetSymbolAddress(&p_wpl, g_wpl);
    cudaGetSymbolAddress(&p_qh, g_qh);
    cudaGetSymbolAddress(&p_ql, g_ql);
    cudaGetSymbolAddress(&p_kh, g_kh);
    cudaGetSymbolAddress(&p_kl, g_kl);
    cudaGetSymbolAddress(&p_vh, g_vth);
    cudaGetSymbolAddress(&p_vl, g_vtl);
    float* qkv = (float*)p_qkv;
    __nv_bfloat16* xh = (__nv_bfloat16*)p_xh;
    __nv_bfloat16* xl = (__nv_bfloat16*)p_xl;
    __nv_bfloat16* yh = (__nv_bfloat16*)p_yh;
    __nv_bfloat16* yl = (__nv_bfloat16*)p_yl;
    __nv_bfloat16* wah = (__nv_bfloat16*)p_wah;
    __nv_bfloat16* wal = (__nv_bfloat16*)p_wal;
    __nv_bfloat16* wph = (__nv_bfloat16*)p_wph;
    __nv_bfloat16* wpl = (__nv_bfloat16*)p_wpl;
    __nv_bfloat16* qh = (__nv_bfloat16*)p_qh;
    __nv_bfloat16* ql = (__nv_bfloat16*)p_ql;
    __nv_bfloat16* kh = (__nv_bfloat16*)p_kh;
    __nv_bfloat16* kl = (__nv_bfloat16*)p_kl;
    __nv_bfloat16* vth = (__nv_bfloat16*)p_vh;
    __nv_bfloat16* vtl = (__nv_bfloat16*)p_vl;

    cudaFuncSetAttribute(tc_gemm_bf16,
                         cudaFuncAttributeMaxDynamicSharedMemorySize, SMEM_DYN);
    cudaFuncSetAttribute(attn_mma_kernel,
                         cudaFuncAttributeMaxDynamicSharedMemorySize, ATT_SMEM);

    // 0) prepasses
    split_kernel<<<(NTOK * DMODEL / 4) / 256, 256>>>(x, xh, xl);
    {
        dim3 blk(32, 8);
        transpose_split_kernel<<<dim3(QKVROW / 32, DMODEL / 32), blk>>>(
            W_attn, wah, wal, DMODEL, QKVROW);
        transpose_split_kernel<<<dim3(DMODEL / 32, DMODEL / 32), blk>>>(
            W_proj, wph, wpl, DMODEL, DMODEL);
    }

    // 1) qkv = x @ W_attn
    {
        dim3 grid(QKVROW / 128, NTOK / 128);
        tc_gemm_bf16<<<grid, 256, SMEM_DYN>>>(xh, xl, wah, wal, qkv,
                                              NTOK, QKVROW, DMODEL);
    }

    // 2) split q/k, split+transpose v
    qk_split_kernel<<<(NTOK * 2048 / 4) / 256, 256>>>(qkv, qh, ql, kh, kl);
    {
        dim3 blk(32, 8);
        v_split_T_kernel<<<dim3(SEQ / 32, HD / 32, BATCH * NHEAD), blk>>>(qkv, vth, vtl);
    }

    // 3) attention -> y (bf16 hi/lo)
    {
        dim3 grid(SEQ / 128, NHEAD, BATCH);
        attn_mma_kernel<<<grid, 256, ATT_SMEM>>>(qh, ql, kh, kl, vth, vtl, yh, yl);
    }

    // 4) out = y @ W_proj
    {
        dim3 grid(DMODEL / 128, NTOK / 128);
        tc_gemm_bf16<<<grid, 256, SMEM_DYN>>>(yh, yl, wph, wpl, out,
                                              NTOK, DMODEL, DMODEL);
    }
}

// round 13
// speedup vs baseline: 1.8200x; 1.0582x over previous
#include <cuda_runtime.h>
#include <cuda_bf16.h>
#include <math.h>
#include <stdint.h>

// Problem constants
#define DMODEL 1024
#define NHEAD  16
#define HD     64
#define BATCH  4
#define SEQ    2048
#define NTOK   (BATCH * SEQ)          // 8192
#define QKVROW (3 * DMODEL)           // 3072

// Scratch (device globals: allocation-guard safe)
__device__ float g_qkv[(size_t)NTOK * QKVROW];
__device__ __nv_bfloat16 g_xh[(size_t)NTOK * DMODEL];
__device__ __nv_bfloat16 g_xl[(size_t)NTOK * DMODEL];
__device__ __nv_bfloat16 g_yh[(size_t)NTOK * DMODEL];
__device__ __nv_bfloat16 g_yl[(size_t)NTOK * DMODEL];
__device__ __nv_bfloat16 g_wah[(size_t)QKVROW * DMODEL];
__device__ __nv_bfloat16 g_wal[(size_t)QKVROW * DMODEL];
__device__ __nv_bfloat16 g_wph[(size_t)DMODEL * DMODEL];
__device__ __nv_bfloat16 g_wpl[(size_t)DMODEL * DMODEL];
__device__ __nv_bfloat16 g_qh[(size_t)NTOK * DMODEL];
__device__ __nv_bfloat16 g_ql[(size_t)NTOK * DMODEL];
__device__ __nv_bfloat16 g_kh[(size_t)NTOK * DMODEL];
__device__ __nv_bfloat16 g_kl[(size_t)NTOK * DMODEL];
__device__ __nv_bfloat16 g_vth[(size_t)BATCH * NHEAD * HD * SEQ]; // [b,h,d,T]
__device__ __nv_bfloat16 g_vtl[(size_t)BATCH * NHEAD * HD * SEQ];

// ---------------------------------------------------------------------------
// PTX helpers
// ---------------------------------------------------------------------------
__device__ __forceinline__ uint32_t smem_u32(const void* p) {
    uint32_t a;
    asm("{ .reg .u64 t; cvta.to.shared.u64 t, %1; cvt.u32.u64 %0, t; }"
        : "=r"(a) : "l"(p));
    return a;
}

__device__ __forceinline__ void ldsm4(uint32_t* r, uint32_t addr) {
    asm volatile("ldmatrix.sync.aligned.m8n8.x4.shared.b16 {%0,%1,%2,%3}, [%4];"
        : "=r"(r[0]), "=r"(r[1]), "=r"(r[2]), "=r"(r[3]) : "r"(addr));
}

__device__ __forceinline__ void mma_bf16(float* c, const uint32_t* a,
                                         const uint32_t* b) {
    asm volatile(
        "mma.sync.aligned.m16n8k16.row.col.f32.bf16.bf16.f32 "
        "{%0,%1,%2,%3}, {%4,%5,%6,%7}, {%8,%9}, {%0,%1,%2,%3};"
        : "+f"(c[0]), "+f"(c[1]), "+f"(c[2]), "+f"(c[3])
        : "r"(a[0]), "r"(a[1]), "r"(a[2]), "r"(a[3]), "r"(b[0]), "r"(b[1]));
}

__device__ __forceinline__ void cp16(uint32_t dst, const void* src) {
    asm volatile("cp.async.cg.shared.global [%0], [%1], 16;"
        :: "r"(dst), "l"(src));
}
#define CP_COMMIT() asm volatile("cp.async.commit_group;" ::: "memory")
#define CP_WAIT1()  asm volatile("cp.async.wait_group 1;" ::: "memory")
#define CP_WAIT0()  asm volatile("cp.async.wait_group 0;" ::: "memory")

__device__ __forceinline__ uint32_t packbf(__nv_bfloat16 a, __nv_bfloat16 b) {
    __nv_bfloat162 t = __halves2bfloat162(a, b);
    return *(uint32_t*)&t;
}

__device__ __forceinline__ void split4(float4 v, uint2& hi, uint2& lo) {
    __nv_bfloat16 hx = __float2bfloat16_rn(v.x);
    __nv_bfloat16 hy = __float2bfloat16_rn(v.y);
    __nv_bfloat16 hz = __float2bfloat16_rn(v.z);
    __nv_bfloat16 hw = __float2bfloat16_rn(v.w);
    __nv_bfloat16 lx = __float2bfloat16_rn(v.x - __bfloat162float(hx));
    __nv_bfloat16 ly = __float2bfloat16_rn(v.y - __bfloat162float(hy));
    __nv_bfloat16 lz = __float2bfloat16_rn(v.z - __bfloat162float(hz));
    __nv_bfloat16 lw = __float2bfloat16_rn(v.w - __bfloat162float(hw));
    hi.x = packbf(hx, hy); hi.y = packbf(hz, hw);
    lo.x = packbf(lx, ly); lo.y = packbf(lz, lw);
}

__device__ __forceinline__ uint32_t ld32(const __nv_bfloat16* p) {
    return *(const uint32_t*)p;
}

// ---------------------------------------------------------------------------
// Prepass: elementwise split fp32 -> bf16 hi/lo
// ---------------------------------------------------------------------------
__global__ void __launch_bounds__(256) split_kernel(
    const float* __restrict__ A,
    __nv_bfloat16* __restrict__ Ah, __nv_bfloat16* __restrict__ Al)
{
    const size_t i4 = ((size_t)blockIdx.x * 256 + threadIdx.x) * 4;
    float4 v = *(const float4*)(A + i4);
    uint2 hi, lo;
    split4(v, hi, lo);
    *(uint2*)(Ah + i4) = hi;
    *(uint2*)(Al + i4) = lo;
}

// ---------------------------------------------------------------------------
// Prepass: fused transpose + split.
// ---------------------------------------------------------------------------
__global__ void __launch_bounds__(256) transpose_split_kernel(
    const float* __restrict__ W,
    __nv_bfloat16* __restrict__ Wth, __nv_bfloat16* __restrict__ Wtl,
    int K, int N)
{
    __shared__ float t[32][33];
    const int tx = threadIdx.x;
    const int ty = threadIdx.y;
    const int n0 = blockIdx.x * 32;
    const int k0 = blockIdx.y * 32;
    #pragma unroll
    for (int j = 0; j < 32; j += 8)
        t[ty + j][tx] = W[(size_t)(k0 + ty + j) * N + n0 + tx];
    __syncthreads();
    #pragma unroll
    for (int j = 0; j < 32; j += 8) {
        const float v = t[tx][ty + j];
        __nv_bfloat16 hi = __float2bfloat16_rn(v);
        __nv_bfloat16 lo = __float2bfloat16_rn(v - __bfloat162float(hi));
        const size_t o = (size_t)(n0 + ty + j) * K + k0 + tx;
        Wth[o] = hi;
        Wtl[o] = lo;
    }
}

// ---------------------------------------------------------------------------
// bf16 GEMM (3-term), 128x128 tile, BK=32.
// 3-stage cp.async pipeline, ONE __syncthreads per iteration.
// SMEM row = 128B = [hi: 4x16B chunks | lo: 4x16B chunks], XOR swizzle
// (chunk ^= row&7) -> conflict-free ldmatrix, no padding.
// Regions per stage: A (128 rows), B (128 rows): 2*16384 = 32768B.
// 3 stages = 98304B/CTA; 2 CTAs/SM = 192KB <= 228KB.
// ---------------------------------------------------------------------------
#define GROWB    128                  // bytes per smem row
#define GREGA    (128 * GROWB)        // 16384 per region
#define GBUF     (2 * GREGA)          // 32768 per stage
#define GSTAGES  3
#define SMEM_DYN (GSTAGES * GBUF)     // 98304

__global__ void __launch_bounds__(256, 2) tc_gemm_bf16(
    const __nv_bfloat16* __restrict__ Ah, const __nv_bfloat16* __restrict__ Al,
    const __nv_bfloat16* __restrict__ Bh, const __nv_bfloat16* __restrict__ Bl,
    float* __restrict__ C, int M, int N, int K)
{
    extern __shared__ __align__(16) char dsm[];

    const int tid = threadIdx.x;
    const int wid = tid >> 5;
    const int lid = tid & 31;
    const int m0 = blockIdx.y * 128;
    const int n0 = blockIdx.x * 128;

    const int Wm = (wid >> 2) * 64;
    const int Wn = (wid & 3) * 32;

    const uint32_t sb = smem_u32(dsm);

    const int l16 = lid & 15;
    const int kh  = lid >> 4;            // A k-half (chunk bit)
    const int bl8 = lid & 7;
    const int bkh = (lid >> 3) & 1;      // B k-half
    const int bnh = lid >> 4;            // B n-half

    // loader mapping: 8 passes x 4096B. row=(p&3)*32 + tid/8, chunk=tid&7
    const int lrow = tid >> 3;           // 0..31
    const int lc   = tid & 7;            // chunk 0..7

    auto load_tile = [&](int stage, int k0) {
        const uint32_t buf = sb + (uint32_t)stage * GBUF;
        #pragma unroll
        for (int p = 0; p < 8; p++) {
            const int region = p >> 2;               // 0=A, 1=B
            const int row = ((p & 3) << 5) + lrow;   // 0..127
            const uint32_t dst = buf + region * GREGA + row * GROWB
                               + ((lc ^ (row & 7)) << 4);
            const __nv_bfloat16* src;
            if (region == 0)
                src = (lc < 4 ? Ah + (size_t)(m0 + row) * K + k0 + lc * 8
                              : Al + (size_t)(m0 + row) * K + k0 + (lc - 4) * 8);
            else
                src = (lc < 4 ? Bh + (size_t)(n0 + row) * K + k0 + lc * 8
                              : Bl + (size_t)(n0 + row) * K + k0 + (lc - 4) * 8);
            cp16(dst, src);
        }
        CP_COMMIT();
    };

    float acc[4][4][4];
    #pragma unroll
    for (int i = 0; i < 4; i++)
        #pragma unroll
        for (int j = 0; j < 4; j++)
            #pragma unroll
            for (int c = 0; c < 4; c++) acc[i][j][c] = 0.0f;

    const int NIT = K >> 5;
    load_tile(0, 0);
    if (NIT > 1) load_tile(1, 32);

    int stage = 0;
    for (int it = 0; it < NIT; it++) {
        if (it + 1 < NIT) { CP_WAIT1(); } else { CP_WAIT0(); }
        __syncthreads();

        // issue next-next tile load early (buffer was last read at it-1,
        // all warps are past that point thanks to the barrier above)
        if (it + 2 < NIT) {
            int ns = stage + 2; if (ns >= GSTAGES) ns -= GSTAGES;
            load_tile(ns, (it + 2) * 32);
        }

        const uint32_t bufA = sb + (uint32_t)stage * GBUF;
        const uint32_t bufB = bufA + GREGA;

        #pragma unroll
        for (int ks = 0; ks < 2; ks++) {
            // A: hi chunk = 2*ks + kh, lo chunk = 4 + 2*ks + kh
            uint32_t ah[4][4], al[4][4];
            #pragma unroll
            for (int mt = 0; mt < 4; mt++) {
                const int row = Wm + mt * 16 + l16;
                const uint32_t rb = bufA + (uint32_t)row * GROWB;
                const int r7 = row & 7;
                ldsm4(ah[mt], rb + (uint32_t)(((2 * ks + kh)     ^ r7) << 4));
                ldsm4(al[mt], rb + (uint32_t)(((4 + 2 * ks + kh) ^ r7) << 4));
            }
            uint32_t bh[2][4], bl[2][4];
            #pragma unroll
            for (int ng = 0; ng < 2; ng++) {
                const int row = Wn + ng * 16 + bl8 + bnh * 8;
                const uint32_t rb = bufB + (uint32_t)row * GROWB;
                const int r7 = row & 7;
                ldsm4(bh[ng], rb + (uint32_t)(((2 * ks + bkh)     ^ r7) << 4));
                ldsm4(bl[ng], rb + (uint32_t)(((4 + 2 * ks + bkh) ^ r7) << 4));
            }

            // term-major: no accumulator sees back-to-back dependent mma
            #pragma unroll
            for (int term = 0; term < 3; term++) {
                #pragma unroll
                for (int mt = 0; mt < 4; mt++)
                    #pragma unroll
                    for (int ng = 0; ng < 2; ng++)
                        #pragma unroll
                        for (int hf = 0; hf < 2; hf++) {
                            float* c = acc[mt][ng * 2 + hf];
                            const uint32_t* af = (term == 2) ? al[mt] : ah[mt];
                            const uint32_t* bsrc = (term == 1) ? bl[ng] : bh[ng];
                            const uint32_t bf[2] = { bsrc[hf * 2], bsrc[hf * 2 + 1] };
                            mma_bf16(c, af, bf);
                        }
            }
        }

        if (++stage == GSTAGES) stage = 0;
    }

    const int g  = lid >> 2;
    const int tg = (lid & 3) * 2;
    #pragma unroll
    for (int mt = 0; mt < 4; mt++) {
        #pragma unroll
        for (int nt = 0; nt < 4; nt++) {
            const int mrow = m0 + Wm + mt * 16 + g;
            const int ncol = n0 + Wn + nt * 8 + tg;
            float2 v0 = make_float2(acc[mt][nt][0], acc[mt][nt][1]);
            float2 v1 = make_float2(acc[mt][nt][2], acc[mt][nt][3]);
            *(float2*)(C + (size_t)mrow * N + ncol)       = v0;
            *(float2*)(C + (size_t)(mrow + 8) * N + ncol) = v1;
        }
    }
}

// ---------------------------------------------------------------------------
// Prepass: split Q (scaled) / K into bf16 hi/lo.
// ---------------------------------------------------------------------------
#define QSCALE (0.125f * 1.44269504088896f)

__global__ void __launch_bounds__(256) qk_split_kernel(
    const float* __restrict__ qkv,
    __nv_bfloat16* __restrict__ qhp, __nv_bfloat16* __restrict__ qlp,
    __nv_bfloat16* __restrict__ khp, __nv_bfloat16* __restrict__ klp)
{
    const int idx = blockIdx.x * 256 + threadIdx.x;
    const int tok = idx >> 9;
    const int c4  = (idx & 511) * 4;
    float4 v = *(const float4*)(qkv + (size_t)tok * QKVROW + c4);
    uint2 hi, lo;
    if (c4 < DMODEL) {
        v.x *= QSCALE; v.y *= QSCALE; v.z *= QSCALE; v.w *= QSCALE;
        split4(v, hi, lo);
        *(uint2*)(qhp + (size_t)tok * DMODEL + c4) = hi;
        *(uint2*)(qlp + (size_t)tok * DMODEL + c4) = lo;
    } else {
        split4(v, hi, lo);
        *(uint2*)(khp + (size_t)tok * DMODEL + c4 - DMODEL) = hi;
        *(uint2*)(klp + (size_t)tok * DMODEL + c4 - DMODEL) = lo;
    }
}

// ---------------------------------------------------------------------------
// Prepass: V -> transposed [b,h,d,T] bf16 hi/lo.
// ---------------------------------------------------------------------------
__global__ void __launch_bounds__(256) v_split_T_kernel(
    const float* __restrict__ qkv,
    __nv_bfloat16* __restrict__ vthp, __nv_bfloat16* __restrict__ vtlp)
{
    __shared__ float t[32][33];
    const int tx = threadIdx.x;
    const int ty = threadIdx.y;
    const int bh = blockIdx.z;
    const int b  = bh >> 4;
    const int h  = bh & 15;
    const int d0 = blockIdx.y * 32;
    const int t0 = blockIdx.x * 32;

    const size_t col = 2 * DMODEL + h * HD + d0 + tx;
    #pragma unroll
    for (int j = 0; j < 32; j += 8)
        t[ty + j][tx] = qkv[(size_t)(b * SEQ + t0 + ty + j) * QKVROW + col];
    __syncthreads();
    #pragma unroll
    for (int j = 0; j < 32; j += 8) {
        const float v = t[tx][ty + j];
        __nv_bfloat16 hi = __float2bfloat16_rn(v);
        __nv_bfloat16 lo = __float2bfloat16_rn(v - __bfloat162float(hi));
        const size_t o = (size_t)(bh * HD + d0 + ty + j) * SEQ + t0 + tx;
        vthp[o] = hi;
        vtlp[o] = lo;
    }
}

// ---------------------------------------------------------------------------
// Flash attention via mma.sync bf16 3-term (unchanged).
// ---------------------------------------------------------------------------
#define KSTR    144
#define REGION  (64 * KSTR)
#define ABUF    (4 * REGION)
#define ATT_SMEM (2 * ABUF)

__global__ void __launch_bounds__(256) attn_mma_kernel(
    const __nv_bfloat16* __restrict__ qh, const __nv_bfloat16* __restrict__ ql,
    const __nv_bfloat16* __restrict__ kh, const __nv_bfloat16* __restrict__ kl,
    const __nv_bfloat16* __restrict__ vth, const __nv_bfloat16* __restrict__ vtl,
    __nv_bfloat16* __restrict__ yh, __nv_bfloat16* __restrict__ yl)
{
    extern __shared__ __align__(16) char asm_[];

    const int tid = threadIdx.x;
    const int wid = tid >> 5;
    const int lid = tid & 31;
    const int qt = gridDim.x - 1 - blockIdx.x;
    const int h  = blockIdx.y;
    const int b  = blockIdx.z;
    const int q0 = qt * 128;
    const int NT = 2 * (qt + 1);

    const uint32_t sb = smem_u32(asm_);

    const int g  = lid >> 2;
    const int c2 = (lid & 3) * 2;
    const int bl8 = lid & 7;
    const int bkh = (lid >> 3) & 1;
    const int bnh = lid >> 4;

    uint32_t aqh[4][4], aql[4][4];
    {
        const size_t r0 = (size_t)(b * SEQ + q0 + wid * 16 + g) * DMODEL + h * HD;
        const size_t r1 = r0 + 8 * DMODEL;
        #pragma unroll
        for (int ks = 0; ks < 4; ks++) {
            const int k0 = ks * 16 + c2;
            aqh[ks][0] = ld32(qh + r0 + k0);
            aqh[ks][1] = ld32(qh + r1 + k0);
            aqh[ks][2] = ld32(qh + r0 + k0 + 8);
            aqh[ks][3] = ld32(qh + r1 + k0 + 8);
            aql[ks][0] = ld32(ql + r0 + k0);
            aql[ks][1] = ld32(ql + r1 + k0);
            aql[ks][2] = ld32(ql + r0 + k0 + 8);
            aql[ks][3] = ld32(ql + r1 + k0 + 8);
        }
    }

    const size_t kbase = (size_t)(b * SEQ) * DMODEL + h * HD;
    const size_t vbase = (size_t)((b * NHEAD + h) * HD) * SEQ;

    auto load_tile = [&](uint32_t buf, int kt) {
        const int ch = tid & 7;
        const int rr = tid >> 3;
        #pragma unroll
        for (int p = 0; p < 8; p++) {
            const int region = p >> 1;
            const int row = ((p & 1) << 5) + rr;
            const uint32_t dst = buf + region * REGION + row * KSTR + ch * 16;
            const __nv_bfloat16* src;
            if (region == 0)
                src = kh + kbase + (size_t)(kt * 64 + row) * DMODEL + ch * 8;
            else if (region == 1)
                src = kl + kbase + (size_t)(kt * 64 + row) * DMODEL + ch * 8;
            else if (region == 2)
                src = vth + vbase + (size_t)row * SEQ + kt * 64 + ch * 8;
            else
                src = vtl + vbase + (size_t)row * SEQ + kt * 64 + ch * 8;
            cp16(dst, src);
        }
        CP_COMMIT();
    };

    float O[8][4];
    #pragma unroll
    for (int nt = 0; nt < 8; nt++)
        #pragma unroll
        for (int c = 0; c < 4; c++) O[nt][c] = 0.0f;
    float m0 = -INFINITY, m1 = -INFINITY, l0 = 0.0f, l1 = 0.0f;

    load_tile(sb, 0);
    if (NT > 1) load_tile(sb + ABUF, 1);

    for (int kt = 0; kt < NT; kt++) {
        if (kt + 1 < NT) { CP_WAIT1(); } else { CP_WAIT0(); }
        __syncthreads();

        const uint32_t buf = sb + (uint32_t)(kt & 1) * ABUF;

        float S[8][4];
        #pragma unroll
        for (int nt = 0; nt < 8; nt++)
            #pragma unroll
            for (int c = 0; c < 4; c++) S[nt][c] = 0.0f;

        #pragma unroll
        for (int ks = 0; ks < 4; ks++) {
            const uint32_t koff = (uint32_t)(ks * 16 + bkh * 8) * 2;
            #pragma unroll
            for (int ng = 0; ng < 4; ng++) {
                const uint32_t row = (uint32_t)(ng * 16 + bl8 + bnh * 8) * KSTR + koff;
                uint32_t kbh[4], kbl[4];
                ldsm4(kbh, buf + 0 * REGION + row);
                ldsm4(kbl, buf + 1 * REGION + row);
                #pragma unroll
                for (int hf = 0; hf < 2; hf++) {
                    float* c = S[ng * 2 + hf];
                    const uint32_t b1[2] = { kbh[hf * 2], kbh[hf * 2 + 1] };
                    const uint32_t b2[2] = { kbl[hf * 2], kbl[hf * 2 + 1] };
                    mma_bf16(c, aqh[ks], b1);
                    mma_bf16(c, aqh[ks], b2);
                    mma_bf16(c, aql[ks], b1);
                }
            }
        }

        if (kt >= 2 * qt) {
            const int qr0 = q0 + wid * 16 + g;
            #pragma unroll
            for (int nt = 0; nt < 8; nt++) {
                #pragma unroll
                for (int e = 0; e < 2; e++) {
                    const int key = kt * 64 + nt * 8 + c2 + e;
                    if (key > qr0)     S[nt][e]     = -INFINITY;
                    if (key > qr0 + 8) S[nt][2 + e] = -INFINITY;
                }
            }
        }

        float mx0 = -INFINITY, mx1 = -INFINITY;
        #pragma unroll
        for (int nt = 0; nt < 8; nt++) {
            mx0 = fmaxf(mx0, fmaxf(S[nt][0], S[nt][1]));
            mx1 = fmaxf(mx1, fmaxf(S[nt][2], S[nt][3]));
        }
        #pragma unroll
        for (int off = 1; off <= 2; off <<= 1) {
            mx0 = fmaxf(mx0, __shfl_xor_sync(0xffffffffu, mx0, off));
            mx1 = fmaxf(mx1, __shfl_xor_sync(0xffffffffu, mx1, off));
        }
        const float mn0 = fmaxf(m0, mx0);
        const float mn1 = fmaxf(m1, mx1);
        const float a0 = exp2f(m0 - mn0);
        const float a1 = exp2f(m1 - mn1);
        m0 = mn0; m1 = mn1;

        float rs0 = 0.0f, rs1 = 0.0f;
        #pragma unroll
        for (int nt = 0; nt < 8; nt++) {
            S[nt][0] = exp2f(S[nt][0] - m0);
            S[nt][1] = exp2f(S[nt][1] - m0);
            S[nt][2] = exp2f(S[nt][2] - m1);
            S[nt][3] = exp2f(S[nt][3] - m1);
            rs0 += S[nt][0] + S[nt][1];
            rs1 += S[nt][2] + S[nt][3];
        }
        #pragma unroll
        for (int off = 1; off <= 2; off <<= 1) {
            rs0 += __shfl_xor_sync(0xffffffffu, rs0, off);
            rs1 += __shfl_xor_sync(0xffffffffu, rs1, off);
        }
        l0 = l0 * a0 + rs0;
        l1 = l1 * a1 + rs1;

        #pragma unroll
        for (int nt = 0; nt < 8; nt++) {
            O[nt][0] *= a0; O[nt][1] *= a0;
            O[nt][2] *= a1; O[nt][3] *= a1;
        }

        uint32_t ph[4][4], pl[4][4];
        #pragma unroll
        for (int ks = 0; ks < 4; ks++) {
            #pragma unroll
            for (int r = 0; r < 4; r++) {
                const int nt = ks * 2 + (r >> 1);
                const float p0 = S[nt][(r & 1) * 2 + 0];
                const float p1 = S[nt][(r & 1) * 2 + 1];
                __nv_bfloat16 h0 = __float2bfloat16_rn(p0);
                __nv_bfloat16 h1 = __float2bfloat16_rn(p1);
                __nv_bfloat16 e0 = __float2bfloat16_rn(p0 - __bfloat162float(h0));
                __nv_bfloat16 e1 = __float2bfloat16_rn(p1 - __bfloat162float(h1));
                ph[ks][r] = packbf(h0, h1);
                pl[ks][r] = packbf(e0, e1);
            }
        }

        #pragma unroll
        for (int ks = 0; ks < 4; ks++) {
            const uint32_t koff = (uint32_t)(ks * 16 + bkh * 8) * 2;
            #pragma unroll
            for (int ng = 0; ng < 4; ng++) {
                const uint32_t row = (uint32_t)(ng * 16 + bl8 + bnh * 8) * KSTR + koff;
                uint32_t vbh[4], vbl[4];
                ldsm4(vbh, buf + 2 * REGION + row);
                ldsm4(vbl, buf + 3 * REGION + row);
                #pragma unroll
                for (int hf = 0; hf < 2; hf++) {
                    float* c = O[ng * 2 + hf];
                    const uint32_t b1[2] = { vbh[hf * 2], vbh[hf * 2 + 1] };
                    const uint32_t b2[2] = { vbl[hf * 2], vbl[hf * 2 + 1] };
                    mma_bf16(c, ph[ks], b1);
                    mma_bf16(c, ph[ks], b2);
                    mma_bf16(c, pl[ks], b1);
                }
            }
        }

        __syncthreads();
        if (kt + 2 < NT) load_tile(buf, kt + 2);
    }

    const float inv0 = 1.0f / l0;
    const float inv1 = 1.0f / l1;
    const size_t o0 = (size_t)(b * SEQ + q0 + wid * 16 + g) * DMODEL + h * HD;
    const size_t o1 = o0 + 8 * DMODEL;
    #pragma unroll
    for (int nt = 0; nt < 8; nt++) {
        const float v00 = O[nt][0] * inv0, v01 = O[nt][1] * inv0;
        const float v10 = O[nt][2] * inv1, v11 = O[nt][3] * inv1;
        __nv_bfloat16 h00 = __float2bfloat16_rn(v00);
        __nv_bfloat16 h01 = __float2bfloat16_rn(v01);
        __nv_bfloat16 h10 = __float2bfloat16_rn(v10);
        __nv_bfloat16 h11 = __float2bfloat16_rn(v11);
        *(uint32_t*)(yh + o0 + nt * 8 + c2) = packbf(h00, h01);
        *(uint32_t*)(yh + o1 + nt * 8 + c2) = packbf(h10, h11);
        *(uint32_t*)(yl + o0 + nt * 8 + c2) = packbf(
            __float2bfloat16_rn(v00 - __bfloat162float(h00)),
            __float2bfloat16_rn(v01 - __bfloat162float(h01)));
        *(uint32_t*)(yl + o1 + nt * 8 + c2) = packbf(
            __float2bfloat16_rn(v10 - __bfloat162float(h10)),
            __float2bfloat16_rn(v11 - __bfloat162float(h11)));
    }
}

// ---------------------------------------------------------------------------
// Launch
// ---------------------------------------------------------------------------
extern "C" void kernel_launch(void* const* d_in, const int* in_sizes, int n_in,
                              void* d_out, int out_size)
{
    const float* x      = (const float*)d_in[0];
    const float* W_attn = (const float*)d_in[1];
    const float* W_proj = (const float*)d_in[2];
    float* out = (float*)d_out;

    void *p_qkv, *p_xh, *p_xl, *p_yh, *p_yl, *p_wah, *p_wal, *p_wph, *p_wpl;
    void *p_qh, *p_ql, *p_kh, *p_kl, *p_vh, *p_vl;
    cudaGetSymbolAddress(&p_qkv, g_qkv);
    cudaGetSymbolAddress(&p_xh, g_xh);
    cudaGetSymbolAddress(&p_xl, g_xl);
    cudaGetSymbolAddress(&p_yh, g_yh);
    cudaGetSymbolAddress(&p_yl, g_yl);
    cudaGetSymbolAddress(&p_wah, g_wah);
    cudaGetSymbolAddress(&p_wal, g_wal);
    cudaGetSymbolAddress(&p_wph, g_wph);
    cudaGetSymbolAddress(&p_wpl, g_wpl);
    cudaGetSymbolAddress(&p_qh, g_qh);
    cudaGetSymbolAddress(&p_ql, g_ql);
    cudaGetSymbolAddress(&p_kh, g_kh);
    cudaGetSymbolAddress(&p_kl, g_kl);
    cudaGetSymbolAddress(&p_vh, g_vth);
    cudaGetSymbolAddress(&p_vl, g_vtl);
    float* qkv = (float*)p_qkv;
    __nv_bfloat16* xh = (__nv_bfloat16*)p_xh;
    __nv_bfloat16* xl = (__nv_bfloat16*)p_xl;
    __nv_bfloat16* yh = (__nv_bfloat16*)p_yh;
    __nv_bfloat16* yl = (__nv_bfloat16*)p_yl;
    __nv_bfloat16* wah = (__nv_bfloat16*)p_wah;
    __nv_bfloat16* wal = (__nv_bfloat16*)p_wal;
    __nv_bfloat16* wph = (__nv_bfloat16*)p_wph;
    __nv_bfloat16* wpl = (__nv_bfloat16*)p_wpl;
    __nv_bfloat16* qh = (__nv_bfloat16*)p_qh;
    __nv_bfloat16* ql = (__nv_bfloat16*)p_ql;
    __nv_bfloat16* kh = (__nv_bfloat16*)p_kh;
    __nv_bfloat16* kl = (__nv_bfloat16*)p_kl;
    __nv_bfloat16* vth = (__nv_bfloat16*)p_vh;
    __nv_bfloat16* vtl = (__nv_bfloat16*)p_vl;

    cudaFuncSetAttribute(tc_gemm_bf16,
                         cudaFuncAttributeMaxDynamicSharedMemorySize, SMEM_DYN);
    cudaFuncSetAttribute(attn_mma_kernel,
                         cudaFuncAttributeMaxDynamicSharedMemorySize, ATT_SMEM);

    // 0) prepasses
    split_kernel<<<(NTOK * DMODEL / 4) / 256, 256>>>(x, xh, xl);
    {
        dim3 blk(32, 8);
        transpose_split_kernel<<<dim3(QKVROW / 32, DMODEL / 32), blk>>>(
            W_attn, wah, wal, DMODEL, QKVROW);
        transpose_split_kernel<<<dim3(DMODEL / 32, DMODEL / 32), blk>>>(
            W_proj, wph, wpl, DMODEL, DMODEL);
    }

    // 1) qkv = x @ W_attn
    {
        dim3 grid(QKVROW / 128, NTOK / 128);
        tc_gemm_bf16<<<grid, 256, SMEM_DYN>>>(xh, xl, wah, wal, qkv,
                                              NTOK, QKVROW, DMODEL);
    }

    // 2) split q/k, split+transpose v
    qk_split_kernel<<<(NTOK * 2048 / 4) / 256, 256>>>(qkv, qh, ql, kh, kl);
    {
        dim3 blk(32, 8);
        v_split_T_kernel<<<dim3(SEQ / 32, HD / 32, BATCH * NHEAD), blk>>>(qkv, vth, vtl);
    }

    // 3) attention -> y (bf16 hi/lo)
    {
        dim3 grid(SEQ / 128, NHEAD, BATCH);
        attn_mma_kernel<<<grid, 256, ATT_SMEM>>>(qh, ql, kh, kl, vth, vtl, yh, yl);
    }

    // 4) out = y @ W_proj
    {
        dim3 grid(DMODEL / 128, NTOK / 128);
        tc_gemm_bf16<<<grid, 256, SMEM_DYN>>>(yh, yl, wph, wpl, out,
                                              NTOK, DMODEL, DMODEL);
    }
}

// round 14
// speedup vs baseline: 1.8280x; 1.0044x over previous
#include <cuda_runtime.h>
#include <cuda_bf16.h>
#include <math.h>
#include <stdint.h>

// Problem constants
#define DMODEL 1024
#define NHEAD  16
#define HD     64
#define BATCH  4
#define SEQ    2048
#define NTOK   (BATCH * SEQ)          // 8192
#define QKVROW (3 * DMODEL)           // 3072

// Scratch (device globals: allocation-guard safe)
__device__ float g_qkv[(size_t)NTOK * QKVROW];
__device__ __nv_bfloat16 g_xh[(size_t)NTOK * DMODEL];
__device__ __nv_bfloat16 g_xl[(size_t)NTOK * DMODEL];
__device__ __nv_bfloat16 g_yh[(size_t)NTOK * DMODEL];
__device__ __nv_bfloat16 g_yl[(size_t)NTOK * DMODEL];
__device__ __nv_bfloat16 g_wah[(size_t)QKVROW * DMODEL];
__device__ __nv_bfloat16 g_wal[(size_t)QKVROW * DMODEL];
__device__ __nv_bfloat16 g_wph[(size_t)DMODEL * DMODEL];
__device__ __nv_bfloat16 g_wpl[(size_t)DMODEL * DMODEL];
__device__ __nv_bfloat16 g_qh[(size_t)NTOK * DMODEL];
__device__ __nv_bfloat16 g_ql[(size_t)NTOK * DMODEL];
__device__ __nv_bfloat16 g_kh[(size_t)NTOK * DMODEL];
__device__ __nv_bfloat16 g_kl[(size_t)NTOK * DMODEL];
__device__ __nv_bfloat16 g_vth[(size_t)BATCH * NHEAD * HD * SEQ]; // [b,h,d,T]
__device__ __nv_bfloat16 g_vtl[(size_t)BATCH * NHEAD * HD * SEQ];

// ---------------------------------------------------------------------------
// PTX helpers
// ---------------------------------------------------------------------------
__device__ __forceinline__ uint32_t smem_u32(const void* p) {
    uint32_t a;
    asm("{ .reg .u64 t; cvta.to.shared.u64 t, %1; cvt.u32.u64 %0, t; }"
        : "=r"(a) : "l"(p));
    return a;
}

__device__ __forceinline__ void ldsm4(uint32_t* r, uint32_t addr) {
    asm volatile("ldmatrix.sync.aligned.m8n8.x4.shared.b16 {%0,%1,%2,%3}, [%4];"
        : "=r"(r[0]), "=r"(r[1]), "=r"(r[2]), "=r"(r[3]) : "r"(addr));
}

__device__ __forceinline__ void mma_bf16(float* c, const uint32_t* a,
                                         const uint32_t* b) {
    asm volatile(
        "mma.sync.aligned.m16n8k16.row.col.f32.bf16.bf16.f32 "
        "{%0,%1,%2,%3}, {%4,%5,%6,%7}, {%8,%9}, {%0,%1,%2,%3};"
        : "+f"(c[0]), "+f"(c[1]), "+f"(c[2]), "+f"(c[3])
        : "r"(a[0]), "r"(a[1]), "r"(a[2]), "r"(a[3]), "r"(b[0]), "r"(b[1]));
}

__device__ __forceinline__ void cp16(uint32_t dst, const void* src) {
    asm volatile("cp.async.cg.shared.global [%0], [%1], 16;"
        :: "r"(dst), "l"(src));
}
#define CP_COMMIT() asm volatile("cp.async.commit_group;" ::: "memory")
#define CP_WAIT1()  asm volatile("cp.async.wait_group 1;" ::: "memory")
#define CP_WAIT0()  asm volatile("cp.async.wait_group 0;" ::: "memory")

__device__ __forceinline__ uint32_t packbf(__nv_bfloat16 a, __nv_bfloat16 b) {
    __nv_bfloat162 t = __halves2bfloat162(a, b);
    return *(uint32_t*)&t;
}

__device__ __forceinline__ void split4(float4 v, uint2& hi, uint2& lo) {
    __nv_bfloat16 hx = __float2bfloat16_rn(v.x);
    __nv_bfloat16 hy = __float2bfloat16_rn(v.y);
    __nv_bfloat16 hz = __float2bfloat16_rn(v.z);
    __nv_bfloat16 hw = __float2bfloat16_rn(v.w);
    __nv_bfloat16 lx = __float2bfloat16_rn(v.x - __bfloat162float(hx));
    __nv_bfloat16 ly = __float2bfloat16_rn(v.y - __bfloat162float(hy));
    __nv_bfloat16 lz = __float2bfloat16_rn(v.z - __bfloat162float(hz));
    __nv_bfloat16 lw = __float2bfloat16_rn(v.w - __bfloat162float(hw));
    hi.x = packbf(hx, hy); hi.y = packbf(hz, hw);
    lo.x = packbf(lx, ly); lo.y = packbf(lz, lw);
}

__device__ __forceinline__ uint32_t ld32(const __nv_bfloat16* p) {
    return *(const uint32_t*)p;
}

// ---------------------------------------------------------------------------
// Prepass: elementwise split fp32 -> bf16 hi/lo
// ---------------------------------------------------------------------------
__global__ void __launch_bounds__(256) split_kernel(
    const float* __restrict__ A,
    __nv_bfloat16* __restrict__ Ah, __nv_bfloat16* __restrict__ Al)
{
    const size_t i4 = ((size_t)blockIdx.x * 256 + threadIdx.x) * 4;
    float4 v = *(const float4*)(A + i4);
    uint2 hi, lo;
    split4(v, hi, lo);
    *(uint2*)(Ah + i4) = hi;
    *(uint2*)(Al + i4) = lo;
}

// ---------------------------------------------------------------------------
// Prepass: fused transpose + split.
// ---------------------------------------------------------------------------
__global__ void __launch_bounds__(256) transpose_split_kernel(
    const float* __restrict__ W,
    __nv_bfloat16* __restrict__ Wth, __nv_bfloat16* __restrict__ Wtl,
    int K, int N)
{
    __shared__ float t[32][33];
    const int tx = threadIdx.x;
    const int ty = threadIdx.y;
    const int n0 = blockIdx.x * 32;
    const int k0 = blockIdx.y * 32;
    #pragma unroll
    for (int j = 0; j < 32; j += 8)
        t[ty + j][tx] = W[(size_t)(k0 + ty + j) * N + n0 + tx];
    __syncthreads();
    #pragma unroll
    for (int j = 0; j < 32; j += 8) {
        const float v = t[tx][ty + j];
        __nv_bfloat16 hi = __float2bfloat16_rn(v);
        __nv_bfloat16 lo = __float2bfloat16_rn(v - __bfloat162float(hi));
        const size_t o = (size_t)(n0 + ty + j) * K + k0 + tx;
        Wth[o] = hi;
        Wtl[o] = lo;
    }
}

// ---------------------------------------------------------------------------
// bf16 GEMM (3-term), 128x128 tile, BK=32.  (unchanged from R8)
// ---------------------------------------------------------------------------
#define GROWB    128
#define GREGA    (128 * GROWB)
#define GBUF     (2 * GREGA)          // 32768 per stage
#define GSTAGES  3
#define SMEM_DYN (GSTAGES * GBUF)     // 98304

__global__ void __launch_bounds__(256, 2) tc_gemm_bf16(
    const __nv_bfloat16* __restrict__ Ah, const __nv_bfloat16* __restrict__ Al,
    const __nv_bfloat16* __restrict__ Bh, const __nv_bfloat16* __restrict__ Bl,
    float* __restrict__ C, int M, int N, int K)
{
    extern __shared__ __align__(16) char dsm[];

    const int tid = threadIdx.x;
    const int wid = tid >> 5;
    const int lid = tid & 31;
    const int m0 = blockIdx.y * 128;
    const int n0 = blockIdx.x * 128;

    const int Wm = (wid >> 2) * 64;
    const int Wn = (wid & 3) * 32;

    const uint32_t sb = smem_u32(dsm);

    const int l16 = lid & 15;
    const int kh  = lid >> 4;
    const int bl8 = lid & 7;
    const int bkh = (lid >> 3) & 1;
    const int bnh = lid >> 4;

    const int lrow = tid >> 3;
    const int lc   = tid & 7;

    auto load_tile = [&](int stage, int k0) {
        const uint32_t buf = sb + (uint32_t)stage * GBUF;
        #pragma unroll
        for (int p = 0; p < 8; p++) {
            const int region = p >> 2;
            const int row = ((p & 3) << 5) + lrow;
            const uint32_t dst = buf + region * GREGA + row * GROWB
                               + ((lc ^ (row & 7)) << 4);
            const __nv_bfloat16* src;
            if (region == 0)
                src = (lc < 4 ? Ah + (size_t)(m0 + row) * K + k0 + lc * 8
                              : Al + (size_t)(m0 + row) * K + k0 + (lc - 4) * 8);
            else
                src = (lc < 4 ? Bh + (size_t)(n0 + row) * K + k0 + lc * 8
                              : Bl + (size_t)(n0 + row) * K + k0 + (lc - 4) * 8);
            cp16(dst, src);
        }
        CP_COMMIT();
    };

    float acc[4][4][4];
    #pragma unroll
    for (int i = 0; i < 4; i++)
        #pragma unroll
        for (int j = 0; j < 4; j++)
            #pragma unroll
            for (int c = 0; c < 4; c++) acc[i][j][c] = 0.0f;

    const int NIT = K >> 5;
    load_tile(0, 0);
    if (NIT > 1) load_tile(1, 32);

    int stage = 0;
    for (int it = 0; it < NIT; it++) {
        if (it + 1 < NIT) { CP_WAIT1(); } else { CP_WAIT0(); }
        __syncthreads();

        if (it + 2 < NIT) {
            int ns = stage + 2; if (ns >= GSTAGES) ns -= GSTAGES;
            load_tile(ns, (it + 2) * 32);
        }

        const uint32_t bufA = sb + (uint32_t)stage * GBUF;
        const uint32_t bufB = bufA + GREGA;

        #pragma unroll
        for (int ks = 0; ks < 2; ks++) {
            uint32_t ah[4][4], al[4][4];
            #pragma unroll
            for (int mt = 0; mt < 4; mt++) {
                const int row = Wm + mt * 16 + l16;
                const uint32_t rb = bufA + (uint32_t)row * GROWB;
                const int r7 = row & 7;
                ldsm4(ah[mt], rb + (uint32_t)(((2 * ks + kh)     ^ r7) << 4));
                ldsm4(al[mt], rb + (uint32_t)(((4 + 2 * ks + kh) ^ r7) << 4));
            }
            uint32_t bh[2][4], bl[2][4];
            #pragma unroll
            for (int ng = 0; ng < 2; ng++) {
                const int row = Wn + ng * 16 + bl8 + bnh * 8;
                const uint32_t rb = bufB + (uint32_t)row * GROWB;
                const int r7 = row & 7;
                ldsm4(bh[ng], rb + (uint32_t)(((2 * ks + bkh)     ^ r7) << 4));
                ldsm4(bl[ng], rb + (uint32_t)(((4 + 2 * ks + bkh) ^ r7) << 4));
            }

            #pragma unroll
            for (int term = 0; term < 3; term++) {
                #pragma unroll
                for (int mt = 0; mt < 4; mt++)
                    #pragma unroll
                    for (int ng = 0; ng < 2; ng++)
                        #pragma unroll
                        for (int hf = 0; hf < 2; hf++) {
                            float* c = acc[mt][ng * 2 + hf];
                            const uint32_t* af = (term == 2) ? al[mt] : ah[mt];
                            const uint32_t* bsrc = (term == 1) ? bl[ng] : bh[ng];
                            const uint32_t bf[2] = { bsrc[hf * 2], bsrc[hf * 2 + 1] };
                            mma_bf16(c, af, bf);
                        }
            }
        }

        if (++stage == GSTAGES) stage = 0;
    }

    const int g  = lid >> 2;
    const int tg = (lid & 3) * 2;
    #pragma unroll
    for (int mt = 0; mt < 4; mt++) {
        #pragma unroll
        for (int nt = 0; nt < 4; nt++) {
            const int mrow = m0 + Wm + mt * 16 + g;
            const int ncol = n0 + Wn + nt * 8 + tg;
            float2 v0 = make_float2(acc[mt][nt][0], acc[mt][nt][1]);
            float2 v1 = make_float2(acc[mt][nt][2], acc[mt][nt][3]);
            *(float2*)(C + (size_t)mrow * N + ncol)       = v0;
            *(float2*)(C + (size_t)(mrow + 8) * N + ncol) = v1;
        }
    }
}

// ---------------------------------------------------------------------------
// Prepass: split Q (scaled) / K into bf16 hi/lo.
// ---------------------------------------------------------------------------
#define QSCALE (0.125f * 1.44269504088896f)

__global__ void __launch_bounds__(256) qk_split_kernel(
    const float* __restrict__ qkv,
    __nv_bfloat16* __restrict__ qhp, __nv_bfloat16* __restrict__ qlp,
    __nv_bfloat16* __restrict__ khp, __nv_bfloat16* __restrict__ klp)
{
    const int idx = blockIdx.x * 256 + threadIdx.x;
    const int tok = idx >> 9;
    const int c4  = (idx & 511) * 4;
    float4 v = *(const float4*)(qkv + (size_t)tok * QKVROW + c4);
    uint2 hi, lo;
    if (c4 < DMODEL) {
        v.x *= QSCALE; v.y *= QSCALE; v.z *= QSCALE; v.w *= QSCALE;
        split4(v, hi, lo);
        *(uint2*)(qhp + (size_t)tok * DMODEL + c4) = hi;
        *(uint2*)(qlp + (size_t)tok * DMODEL + c4) = lo;
    } else {
        split4(v, hi, lo);
        *(uint2*)(khp + (size_t)tok * DMODEL + c4 - DMODEL) = hi;
        *(uint2*)(klp + (size_t)tok * DMODEL + c4 - DMODEL) = lo;
    }
}

// ---------------------------------------------------------------------------
// Prepass: V -> transposed [b,h,d,T] bf16 hi/lo.
// ---------------------------------------------------------------------------
__global__ void __launch_bounds__(256) v_split_T_kernel(
    const float* __restrict__ qkv,
    __nv_bfloat16* __restrict__ vthp, __nv_bfloat16* __restrict__ vtlp)
{
    __shared__ float t[32][33];
    const int tx = threadIdx.x;
    const int ty = threadIdx.y;
    const int bh = blockIdx.z;
    const int b  = bh >> 4;
    const int h  = bh & 15;
    const int d0 = blockIdx.y * 32;
    const int t0 = blockIdx.x * 32;

    const size_t col = 2 * DMODEL + h * HD + d0 + tx;
    #pragma unroll
    for (int j = 0; j < 32; j += 8)
        t[ty + j][tx] = qkv[(size_t)(b * SEQ + t0 + ty + j) * QKVROW + col];
    __syncthreads();
    #pragma unroll
    for (int j = 0; j < 32; j += 8) {
        const float v = t[tx][ty + j];
        __nv_bfloat16 hi = __float2bfloat16_rn(v);
        __nv_bfloat16 lo = __float2bfloat16_rn(v - __bfloat162float(hi));
        const size_t o = (size_t)(bh * HD + d0 + ty + j) * SEQ + t0 + tx;
        vthp[o] = hi;
        vtlp[o] = lo;
    }
}

// ---------------------------------------------------------------------------
// Flash attention via mma.sync bf16 3-term.
// R9: 3-stage cp.async pipeline, ONE __syncthreads per K-tile.
// Load for kt+2 issues right after the barrier (targets the buffer last
// read at kt-1, protected by that barrier), before the compute phase.
// ---------------------------------------------------------------------------
#define KSTR       144
#define REGION     (64 * KSTR)
#define ABUF       (4 * REGION)       // 36864 per stage
#define ATT_STAGES 3
#define ATT_SMEM   (ATT_STAGES * ABUF)  // 110592

__global__ void __launch_bounds__(256) attn_mma_kernel(
    const __nv_bfloat16* __restrict__ qh, const __nv_bfloat16* __restrict__ ql,
    const __nv_bfloat16* __restrict__ kh, const __nv_bfloat16* __restrict__ kl,
    const __nv_bfloat16* __restrict__ vth, const __nv_bfloat16* __restrict__ vtl,
    __nv_bfloat16* __restrict__ yh, __nv_bfloat16* __restrict__ yl)
{
    extern __shared__ __align__(16) char asm_[];

    const int tid = threadIdx.x;
    const int wid = tid >> 5;
    const int lid = tid & 31;
    const int qt = gridDim.x - 1 - blockIdx.x;
    const int h  = blockIdx.y;
    const int b  = blockIdx.z;
    const int q0 = qt * 128;
    const int NT = 2 * (qt + 1);

    const uint32_t sb = smem_u32(asm_);

    const int g  = lid >> 2;
    const int c2 = (lid & 3) * 2;
    const int bl8 = lid & 7;
    const int bkh = (lid >> 3) & 1;
    const int bnh = lid >> 4;

    uint32_t aqh[4][4], aql[4][4];
    {
        const size_t r0 = (size_t)(b * SEQ + q0 + wid * 16 + g) * DMODEL + h * HD;
        const size_t r1 = r0 + 8 * DMODEL;
        #pragma unroll
        for (int ks = 0; ks < 4; ks++) {
            const int k0 = ks * 16 + c2;
            aqh[ks][0] = ld32(qh + r0 + k0);
            aqh[ks][1] = ld32(qh + r1 + k0);
            aqh[ks][2] = ld32(qh + r0 + k0 + 8);
            aqh[ks][3] = ld32(qh + r1 + k0 + 8);
            aql[ks][0] = ld32(ql + r0 + k0);
            aql[ks][1] = ld32(ql + r1 + k0);
            aql[ks][2] = ld32(ql + r0 + k0 + 8);
            aql[ks][3] = ld32(ql + r1 + k0 + 8);
        }
    }

    const size_t kbase = (size_t)(b * SEQ) * DMODEL + h * HD;
    const size_t vbase = (size_t)((b * NHEAD + h) * HD) * SEQ;

    auto load_tile = [&](int stage, int kt) {
        const uint32_t buf = sb + (uint32_t)stage * ABUF;
        const int ch = tid & 7;
        const int rr = tid >> 3;
        #pragma unroll
        for (int p = 0; p < 8; p++) {
            const int region = p >> 1;
            const int row = ((p & 1) << 5) + rr;
            const uint32_t dst = buf + region * REGION + row * KSTR + ch * 16;
            const __nv_bfloat16* src;
            if (region == 0)
                src = kh + kbase + (size_t)(kt * 64 + row) * DMODEL + ch * 8;
            else if (region == 1)
                src = kl + kbase + (size_t)(kt * 64 + row) * DMODEL + ch * 8;
            else if (region == 2)
                src = vth + vbase + (size_t)row * SEQ + kt * 64 + ch * 8;
            else
                src = vtl + vbase + (size_t)row * SEQ + kt * 64 + ch * 8;
            cp16(dst, src);
        }
        CP_COMMIT();
    };

    float O[8][4];
    #pragma unroll
    for (int nt = 0; nt < 8; nt++)
        #pragma unroll
        for (int c = 0; c < 4; c++) O[nt][c] = 0.0f;
    float m0 = -INFINITY, m1 = -INFINITY, l0 = 0.0f, l1 = 0.0f;

    load_tile(0, 0);
    if (NT > 1) load_tile(1, 1);

    int stage = 0;
    for (int kt = 0; kt < NT; kt++) {
        if (kt + 1 < NT) { CP_WAIT1(); } else { CP_WAIT0(); }
        __syncthreads();

        // issue next-next tile load early (buffer last read at kt-1)
        if (kt + 2 < NT) {
            int ns = stage + 2; if (ns >= ATT_STAGES) ns -= ATT_STAGES;
            load_tile(ns, kt + 2);
        }

        const uint32_t buf = sb + (uint32_t)stage * ABUF;

        float S[8][4];
        #pragma unroll
        for (int nt = 0; nt < 8; nt++)
            #pragma unroll
            for (int c = 0; c < 4; c++) S[nt][c] = 0.0f;

        #pragma unroll
        for (int ks = 0; ks < 4; ks++) {
            const uint32_t koff = (uint32_t)(ks * 16 + bkh * 8) * 2;
            #pragma unroll
            for (int ng = 0; ng < 4; ng++) {
                const uint32_t row = (uint32_t)(ng * 16 + bl8 + bnh * 8) * KSTR + koff;
                uint32_t kbh[4], kbl[4];
                ldsm4(kbh, buf + 0 * REGION + row);
                ldsm4(kbl, buf + 1 * REGION + row);
                #pragma unroll
                for (int hf = 0; hf < 2; hf++) {
                    float* c = S[ng * 2 + hf];
                    const uint32_t b1[2] = { kbh[hf * 2], kbh[hf * 2 + 1] };
                    const uint32_t b2[2] = { kbl[hf * 2], kbl[hf * 2 + 1] };
                    mma_bf16(c, aqh[ks], b1);
                    mma_bf16(c, aqh[ks], b2);
                    mma_bf16(c, aql[ks], b1);
                }
            }
        }

        if (kt >= 2 * qt) {
            const int qr0 = q0 + wid * 16 + g;
            #pragma unroll
            for (int nt = 0; nt < 8; nt++) {
                #pragma unroll
                for (int e = 0; e < 2; e++) {
                    const int key = kt * 64 + nt * 8 + c2 + e;
                    if (key > qr0)     S[nt][e]     = -INFINITY;
                    if (key > qr0 + 8) S[nt][2 + e] = -INFINITY;
                }
            }
        }

        float mx0 = -INFINITY, mx1 = -INFINITY;
        #pragma unroll
        for (int nt = 0; nt < 8; nt++) {
            mx0 = fmaxf(mx0, fmaxf(S[nt][0], S[nt][1]));
            mx1 = fmaxf(mx1, fmaxf(S[nt][2], S[nt][3]));
        }
        #pragma unroll
        for (int off = 1; off <= 2; off <<= 1) {
            mx0 = fmaxf(mx0, __shfl_xor_sync(0xffffffffu, mx0, off));
            mx1 = fmaxf(mx1, __shfl_xor_sync(0xffffffffu, mx1, off));
        }
        const float mn0 = fmaxf(m0, mx0);
        const float mn1 = fmaxf(m1, mx1);
        const float a0 = exp2f(m0 - mn0);
        const float a1 = exp2f(m1 - mn1);
        m0 = mn0; m1 = mn1;

        float rs0 = 0.0f, rs1 = 0.0f;
        #pragma unroll
        for (int nt = 0; nt < 8; nt++) {
            S[nt][0] = exp2f(S[nt][0] - m0);
            S[nt][1] = exp2f(S[nt][1] - m0);
            S[nt][2] = exp2f(S[nt][2] - m1);
            S[nt][3] = exp2f(S[nt][3] - m1);
            rs0 += S[nt][0] + S[nt][1];
            rs1 += S[nt][2] + S[nt][3];
        }
        #pragma unroll
        for (int off = 1; off <= 2; off <<= 1) {
            rs0 += __shfl_xor_sync(0xffffffffu, rs0, off);
            rs1 += __shfl_xor_sync(0xffffffffu, rs1, off);
        }
        l0 = l0 * a0 + rs0;
        l1 = l1 * a1 + rs1;

        #pragma unroll
        for (int nt = 0; nt < 8; nt++) {
            O[nt][0] *= a0; O[nt][1] *= a0;
            O[nt][2] *= a1; O[nt][3] *= a1;
        }

        uint32_t ph[4][4], pl[4][4];
        #pragma unroll
        for (int ks = 0; ks < 4; ks++) {
            #pragma unroll
            for (int r = 0; r < 4; r++) {
                const int nt = ks * 2 + (r >> 1);
                const float p0 = S[nt][(r & 1) * 2 + 0];
                const float p1 = S[nt][(r & 1) * 2 + 1];
                __nv_bfloat16 h0 = __float2bfloat16_rn(p0);
                __nv_bfloat16 h1 = __float2bfloat16_rn(p1);
                __nv_bfloat16 e0 = __float2bfloat16_rn(p0 - __bfloat162float(h0));
                __nv_bfloat16 e1 = __float2bfloat16_rn(p1 - __bfloat162float(h1));
                ph[ks][r] = packbf(h0, h1);
                pl[ks][r] = packbf(e0, e1);
            }
        }

        #pragma unroll
        for (int ks = 0; ks < 4; ks++) {
            const uint32_t koff = (uint32_t)(ks * 16 + bkh * 8) * 2;
            #pragma unroll
            for (int ng = 0; ng < 4; ng++) {
                const uint32_t row = (uint32_t)(ng * 16 + bl8 + bnh * 8) * KSTR + koff;
                uint32_t vbh[4], vbl[4];
                ldsm4(vbh, buf + 2 * REGION + row);
                ldsm4(vbl, buf + 3 * REGION + row);
                #pragma unroll
                for (int hf = 0; hf < 2; hf++) {
                    float* c = O[ng * 2 + hf];
                    const uint32_t b1[2] = { vbh[hf * 2], vbh[hf * 2 + 1] };
                    const uint32_t b2[2] = { vbl[hf * 2], vbl[hf * 2 + 1] };
                    mma_bf16(c, ph[ks], b1);
                    mma_bf16(c, ph[ks], b2);
                    mma_bf16(c, pl[ks], b1);
                }
            }
        }

        if (++stage == ATT_STAGES) stage = 0;
    }

    const float inv0 = 1.0f / l0;
    const float inv1 = 1.0f / l1;
    const size_t o0 = (size_t)(b * SEQ + q0 + wid * 16 + g) * DMODEL + h * HD;
    const size_t o1 = o0 + 8 * DMODEL;
    #pragma unroll
    for (int nt = 0; nt < 8; nt++) {
        const float v00 = O[nt][0] * inv0, v01 = O[nt][1] * inv0;
        const float v10 = O[nt][2] * inv1, v11 = O[nt][3] * inv1;
        __nv_bfloat16 h00 = __float2bfloat16_rn(v00);
        __nv_bfloat16 h01 = __float2bfloat16_rn(v01);
        __nv_bfloat16 h10 = __float2bfloat16_rn(v10);
        __nv_bfloat16 h11 = __float2bfloat16_rn(v11);
        *(uint32_t*)(yh + o0 + nt * 8 + c2) = packbf(h00, h01);
        *(uint32_t*)(yh + o1 + nt * 8 + c2) = packbf(h10, h11);
        *(uint32_t*)(yl + o0 + nt * 8 + c2) = packbf(
            __float2bfloat16_rn(v00 - __bfloat162float(h00)),
            __float2bfloat16_rn(v01 - __bfloat162float(h01)));
        *(uint32_t*)(yl + o1 + nt * 8 + c2) = packbf(
            __float2bfloat16_rn(v10 - __bfloat162float(h10)),
            __float2bfloat16_rn(v11 - __bfloat162float(h11)));
    }
}

// ---------------------------------------------------------------------------
// Launch
// ---------------------------------------------------------------------------
extern "C" void kernel_launch(void* const* d_in, const int* in_sizes, int n_in,
                              void* d_out, int out_size)
{
    const float* x      = (const float*)d_in[0];
    const float* W_attn = (const float*)d_in[1];
    const float* W_proj = (const float*)d_in[2];
    float* out = (float*)d_out;

    void *p_qkv, *p_xh, *p_xl, *p_yh, *p_yl, *p_wah, *p_wal, *p_wph, *p_wpl;
    void *p_qh, *p_ql, *p_kh, *p_kl, *p_vh, *p_vl;
    cudaGetSymbolAddress(&p_qkv, g_qkv);
    cudaGetSymbolAddress(&p_xh, g_xh);
    cudaGetSymbolAddress(&p_xl, g_xl);
    cudaGetSymbolAddress(&p_yh, g_yh);
    cudaGetSymbolAddress(&p_yl, g_yl);
    cudaGetSymbolAddress(&p_wah, g_wah);
    cudaGetSymbolAddress(&p_wal, g_wal);
    cudaGetSymbolAddress(&p_wph, g_wph);
    cudaGetSymbolAddress(&p_wpl, g_wpl);
    cudaGetSymbolAddress(&p_qh, g_qh);
    cudaGetSymbolAddress(&p_ql, g_ql);
    cudaGetSymbolAddress(&p_kh, g_kh);
    cudaGetSymbolAddress(&p_kl, g_kl);
    cudaGetSymbolAddress(&p_vh, g_vth);
    cudaGetSymbolAddress(&p_vl, g_vtl);
    float* qkv = (float*)p_qkv;
    __nv_bfloat16* xh = (__nv_bfloat16*)p_xh;
    __nv_bfloat16* xl = (__nv_bfloat16*)p_xl;
    __nv_bfloat16* yh = (__nv_bfloat16*)p_yh;
    __nv_bfloat16* yl = (__nv_bfloat16*)p_yl;
    __nv_bfloat16* wah = (__nv_bfloat16*)p_wah;
    __nv_bfloat16* wal = (__nv_bfloat16*)p_wal;
    __nv_bfloat16* wph = (__nv_bfloat16*)p_wph;
    __nv_bfloat16* wpl = (__nv_bfloat16*)p_wpl;
    __nv_bfloat16* qh = (__nv_bfloat16*)p_qh;
    __nv_bfloat16* ql = (__nv_bfloat16*)p_ql;
    __nv_bfloat16* kh = (__nv_bfloat16*)p_kh;
    __nv_bfloat16* kl = (__nv_bfloat16*)p_kl;
    __nv_bfloat16* vth = (__nv_bfloat16*)p_vh;
    __nv_bfloat16* vtl = (__nv_bfloat16*)p_vl;

    cudaFuncSetAttribute(tc_gemm_bf16,
                         cudaFuncAttributeMaxDynamicSharedMemorySize, SMEM_DYN);
    cudaFuncSetAttribute(attn_mma_kernel,
                         cudaFuncAttributeMaxDynamicSharedMemorySize, ATT_SMEM);

    // 0) prepasses
    split_kernel<<<(NTOK * DMODEL / 4) / 256, 256>>>(x, xh, xl);
    {
        dim3 blk(32, 8);
        transpose_split_kernel<<<dim3(QKVROW / 32, DMODEL / 32), blk>>>(
            W_attn, wah, wal, DMODEL, QKVROW);
        transpose_split_kernel<<<dim3(DMODEL / 32, DMODEL / 32), blk>>>(
            W_proj, wph, wpl, DMODEL, DMODEL);
    }

    // 1) qkv = x @ W_attn
    {
        dim3 grid(QKVROW / 128, NTOK / 128);
        tc_gemm_bf16<<<grid, 256, SMEM_DYN>>>(xh, xl, wah, wal, qkv,
                                              NTOK, QKVROW, DMODEL);
    }

    // 2) split q/k, split+transpose v
    qk_split_kernel<<<(NTOK * 2048 / 4) / 256, 256>>>(qkv, qh, ql, kh, kl);
    {
        dim3 blk(32, 8);
        v_split_T_kernel<<<dim3(SEQ / 32, HD / 32, BATCH * NHEAD), blk>>>(qkv, vth, vtl);
    }

    // 3) attention -> y (bf16 hi/lo)
    {
        dim3 grid(SEQ / 128, NHEAD, BATCH);
        attn_mma_kernel<<<grid, 256, ATT_SMEM>>>(qh, ql, kh, kl, vth, vtl, yh, yl);
    }

    // 4) out = y @ W_proj
    {
        dim3 grid(DMODEL / 128, NTOK / 128);
        tc_gemm_bf16<<<grid, 256, SMEM_DYN>>>(yh, yl, wph, wpl, out,
                                              NTOK, DMODEL, DMODEL);
    }
}

// round 16
// speedup vs baseline: 1.8689x; 1.0224x over previous
#include <cuda_runtime.h>
#include <cuda_bf16.h>
#include <math.h>
#include <stdint.h>

// Problem constants
#define DMODEL 1024
#define NHEAD  16
#define HD     64
#define BATCH  4
#define SEQ    2048
#define NTOK   (BATCH * SEQ)          // 8192
#define QKVROW (3 * DMODEL)           // 3072

// Scratch (device globals: allocation-guard safe)
__device__ float g_qkv[(size_t)NTOK * QKVROW];   // only V region used now
__device__ __nv_bfloat16 g_xh[(size_t)NTOK * DMODEL];
__device__ __nv_bfloat16 g_xl[(size_t)NTOK * DMODEL];
__device__ __nv_bfloat16 g_yh[(size_t)NTOK * DMODEL];
__device__ __nv_bfloat16 g_yl[(size_t)NTOK * DMODEL];
__device__ __nv_bfloat16 g_wah[(size_t)QKVROW * DMODEL];
__device__ __nv_bfloat16 g_wal[(size_t)QKVROW * DMODEL];
__device__ __nv_bfloat16 g_wph[(size_t)DMODEL * DMODEL];
__device__ __nv_bfloat16 g_wpl[(size_t)DMODEL * DMODEL];
__device__ __nv_bfloat16 g_qh[(size_t)NTOK * DMODEL];
__device__ __nv_bfloat16 g_ql[(size_t)NTOK * DMODEL];
__device__ __nv_bfloat16 g_kh[(size_t)NTOK * DMODEL];
__device__ __nv_bfloat16 g_kl[(size_t)NTOK * DMODEL];
__device__ __nv_bfloat16 g_vth[(size_t)BATCH * NHEAD * HD * SEQ]; // [b,h,d,T]
__device__ __nv_bfloat16 g_vtl[(size_t)BATCH * NHEAD * HD * SEQ];

#define QSCALE (0.125f * 1.44269504088896f)

// ---------------------------------------------------------------------------
// PTX helpers
// ---------------------------------------------------------------------------
__device__ __forceinline__ uint32_t smem_u32(const void* p) {
    uint32_t a;
    asm("{ .reg .u64 t; cvta.to.shared.u64 t, %1; cvt.u32.u64 %0, t; }"
        : "=r"(a) : "l"(p));
    return a;
}

__device__ __forceinline__ void ldsm4(uint32_t* r, uint32_t addr) {
    asm volatile("ldmatrix.sync.aligned.m8n8.x4.shared.b16 {%0,%1,%2,%3}, [%4];"
        : "=r"(r[0]), "=r"(r[1]), "=r"(r[2]), "=r"(r[3]) : "r"(addr));
}

__device__ __forceinline__ void mma_bf16(float* c, const uint32_t* a,
                                         const uint32_t* b) {
    asm volatile(
        "mma.sync.aligned.m16n8k16.row.col.f32.bf16.bf16.f32 "
        "{%0,%1,%2,%3}, {%4,%5,%6,%7}, {%8,%9}, {%0,%1,%2,%3};"
        : "+f"(c[0]), "+f"(c[1]), "+f"(c[2]), "+f"(c[3])
        : "r"(a[0]), "r"(a[1]), "r"(a[2]), "r"(a[3]), "r"(b[0]), "r"(b[1]));
}

__device__ __forceinline__ void cp16(uint32_t dst, const void* src) {
    asm volatile("cp.async.cg.shared.global [%0], [%1], 16;"
        :: "r"(dst), "l"(src));
}
#define CP_COMMIT() asm volatile("cp.async.commit_group;" ::: "memory")
#define CP_WAIT1()  asm volatile("cp.async.wait_group 1;" ::: "memory")
#define CP_WAIT0()  asm volatile("cp.async.wait_group 0;" ::: "memory")

__device__ __forceinline__ uint32_t packbf(__nv_bfloat16 a, __nv_bfloat16 b) {
    __nv_bfloat162 t = __halves2bfloat162(a, b);
    return *(uint32_t*)&t;
}

__device__ __forceinline__ void split4(float4 v, uint2& hi, uint2& lo) {
    __nv_bfloat16 hx = __float2bfloat16_rn(v.x);
    __nv_bfloat16 hy = __float2bfloat16_rn(v.y);
    __nv_bfloat16 hz = __float2bfloat16_rn(v.z);
    __nv_bfloat16 hw = __float2bfloat16_rn(v.w);
    __nv_bfloat16 lx = __float2bfloat16_rn(v.x - __bfloat162float(hx));
    __nv_bfloat16 ly = __float2bfloat16_rn(v.y - __bfloat162float(hy));
    __nv_bfloat16 lz = __float2bfloat16_rn(v.z - __bfloat162float(hz));
    __nv_bfloat16 lw = __float2bfloat16_rn(v.w - __bfloat162float(hw));
    hi.x = packbf(hx, hy); hi.y = packbf(hz, hw);
    lo.x = packbf(lx, ly); lo.y = packbf(lz, lw);
}

__device__ __forceinline__ void split2(float a, float b,
                                       uint32_t& hi, uint32_t& lo) {
    __nv_bfloat16 ha = __float2bfloat16_rn(a);
    __nv_bfloat16 hb = __float2bfloat16_rn(b);
    hi = packbf(ha, hb);
    lo = packbf(__float2bfloat16_rn(a - __bfloat162float(ha)),
                __float2bfloat16_rn(b - __bfloat162float(hb)));
}

__device__ __forceinline__ uint32_t ld32(const __nv_bfloat16* p) {
    return *(const uint32_t*)p;
}

// ---------------------------------------------------------------------------
// Prepass: elementwise split fp32 -> bf16 hi/lo
// ---------------------------------------------------------------------------
__global__ void __launch_bounds__(256) split_kernel(
    const float* __restrict__ A,
    __nv_bfloat16* __restrict__ Ah, __nv_bfloat16* __restrict__ Al)
{
    const size_t i4 = ((size_t)blockIdx.x * 256 + threadIdx.x) * 4;
    float4 v = *(const float4*)(A + i4);
    uint2 hi, lo;
    split4(v, hi, lo);
    *(uint2*)(Ah + i4) = hi;
    *(uint2*)(Al + i4) = lo;
}

// ---------------------------------------------------------------------------
// Prepass: fused transpose + split.
// ---------------------------------------------------------------------------
__global__ void __launch_bounds__(256) transpose_split_kernel(
    const float* __restrict__ W,
    __nv_bfloat16* __restrict__ Wth, __nv_bfloat16* __restrict__ Wtl,
    int K, int N)
{
    __shared__ float t[32][33];
    const int tx = threadIdx.x;
    const int ty = threadIdx.y;
    const int n0 = blockIdx.x * 32;
    const int k0 = blockIdx.y * 32;
    #pragma unroll
    for (int j = 0; j < 32; j += 8)
        t[ty + j][tx] = W[(size_t)(k0 + ty + j) * N + n0 + tx];
    __syncthreads();
    #pragma unroll
    for (int j = 0; j < 32; j += 8) {
        const float v = t[tx][ty + j];
        __nv_bfloat16 hi = __float2bfloat16_rn(v);
        __nv_bfloat16 lo = __float2bfloat16_rn(v - __bfloat162float(hi));
        const size_t o = (size_t)(n0 + ty + j) * K + k0 + tx;
        Wth[o] = hi;
        Wtl[o] = lo;
    }
}

// ---------------------------------------------------------------------------
// bf16 GEMM (3-term), 128x128 tile, BK=32, 3-stage cp.async pipeline.
// R10: term-by-term fragment loading (smaller live ranges), and
// mode=1 epilogue writes Q/K as split bf16 (+QSCALE on Q), V as fp32.
// ---------------------------------------------------------------------------
#define GROWB    128
#define GREGA    (128 * GROWB)
#define GBUF     (2 * GREGA)          // 32768 per stage
#define GSTAGES  3
#define SMEM_DYN (GSTAGES * GBUF)     // 98304

__global__ void __launch_bounds__(256, 2) tc_gemm_bf16(
    const __nv_bfloat16* __restrict__ Ah, const __nv_bfloat16* __restrict__ Al,
    const __nv_bfloat16* __restrict__ Bh, const __nv_bfloat16* __restrict__ Bl,
    float* __restrict__ C, int M, int N, int K, int mode,
    __nv_bfloat16* __restrict__ oqh, __nv_bfloat16* __restrict__ oql,
    __nv_bfloat16* __restrict__ okh, __nv_bfloat16* __restrict__ okl)
{
    extern __shared__ __align__(16) char dsm[];

    const int tid = threadIdx.x;
    const int wid = tid >> 5;
    const int lid = tid & 31;
    const int m0 = blockIdx.y * 128;
    const int n0 = blockIdx.x * 128;

    const int Wm = (wid >> 2) * 64;
    const int Wn = (wid & 3) * 32;

    const uint32_t sb = smem_u32(dsm);

    const int l16 = lid & 15;
    const int kh  = lid >> 4;
    const int bl8 = lid & 7;
    const int bkh = (lid >> 3) & 1;
    const int bnh = lid >> 4;

    const int lrow = tid >> 3;
    const int lc   = tid & 7;

    auto load_tile = [&](int stage, int k0) {
        const uint32_t buf = sb + (uint32_t)stage * GBUF;
        #pragma unroll
        for (int p = 0; p < 8; p++) {
            const int region = p >> 2;
            const int row = ((p & 3) << 5) + lrow;
            const uint32_t dst = buf + region * GREGA + row * GROWB
                               + ((lc ^ (row & 7)) << 4);
            const __nv_bfloat16* src;
            if (region == 0)
                src = (lc < 4 ? Ah + (size_t)(m0 + row) * K + k0 + lc * 8
                              : Al + (size_t)(m0 + row) * K + k0 + (lc - 4) * 8);
            else
                src = (lc < 4 ? Bh + (size_t)(n0 + row) * K + k0 + lc * 8
                              : Bl + (size_t)(n0 + row) * K + k0 + (lc - 4) * 8);
            cp16(dst, src);
        }
        CP_COMMIT();
    };

    float acc[4][4][4];
    #pragma unroll
    for (int i = 0; i < 4; i++)
        #pragma unroll
        for (int j = 0; j < 4; j++)
            #pragma unroll
            for (int c = 0; c < 4; c++) acc[i][j][c] = 0.0f;

    const int NIT = K >> 5;
    load_tile(0, 0);
    if (NIT > 1) load_tile(1, 32);

    int stage = 0;
    for (int it = 0; it < NIT; it++) {
        if (it + 1 < NIT) { CP_WAIT1(); } else { CP_WAIT0(); }
        __syncthreads();

        if (it + 2 < NIT) {
            int ns = stage + 2; if (ns >= GSTAGES) ns -= GSTAGES;
            load_tile(ns, (it + 2) * 32);
        }

        const uint32_t bufA = sb + (uint32_t)stage * GBUF;
        const uint32_t bufB = bufA + GREGA;

        #pragma unroll
        for (int ks = 0; ks < 2; ks++) {
            // term 0: A-hi x B-hi (load only those first: small live set)
            uint32_t ah[4][4];
            #pragma unroll
            for (int mt = 0; mt < 4; mt++) {
                const int row = Wm + mt * 16 + l16;
                ldsm4(ah[mt], bufA + (uint32_t)row * GROWB
                              + (uint32_t)(((2 * ks + kh) ^ (row & 7)) << 4));
            }
            uint32_t bh[2][4];
            #pragma unroll
            for (int ng = 0; ng < 2; ng++) {
                const int row = Wn + ng * 16 + bl8 + bnh * 8;
                ldsm4(bh[ng], bufB + (uint32_t)row * GROWB
                              + (uint32_t)(((2 * ks + bkh) ^ (row & 7)) << 4));
            }
            #pragma unroll
            for (int mt = 0; mt < 4; mt++)
                #pragma unroll
                for (int ng = 0; ng < 2; ng++)
                    #pragma unroll
                    for (int hf = 0; hf < 2; hf++) {
                        const uint32_t bf[2] = { bh[ng][hf * 2], bh[ng][hf * 2 + 1] };
                        mma_bf16(acc[mt][ng * 2 + hf], ah[mt], bf);
                    }

            // term 1: A-hi x B-lo
            {
                uint32_t bl[2][4];
                #pragma unroll
                for (int ng = 0; ng < 2; ng++) {
                    const int row = Wn + ng * 16 + bl8 + bnh * 8;
                    ldsm4(bl[ng], bufB + (uint32_t)row * GROWB
                                  + (uint32_t)(((4 + 2 * ks + bkh) ^ (row & 7)) << 4));
                }
                #pragma unroll
                for (int mt = 0; mt < 4; mt++)
                    #pragma unroll
                    for (int ng = 0; ng < 2; ng++)
                        #pragma unroll
                        for (int hf = 0; hf < 2; hf++) {
                            const uint32_t bf[2] = { bl[ng][hf * 2], bl[ng][hf * 2 + 1] };
                            mma_bf16(acc[mt][ng * 2 + hf], ah[mt], bf);
                        }
            }

            // term 2: A-lo x B-hi
            {
                uint32_t al[4][4];
                #pragma unroll
                for (int mt = 0; mt < 4; mt++) {
                    const int row = Wm + mt * 16 + l16;
                    ldsm4(al[mt], bufA + (uint32_t)row * GROWB
                                  + (uint32_t)(((4 + 2 * ks + kh) ^ (row & 7)) << 4));
                }
                #pragma unroll
                for (int mt = 0; mt < 4; mt++)
                    #pragma unroll
                    for (int ng = 0; ng < 2; ng++)
                        #pragma unroll
                        for (int hf = 0; hf < 2; hf++) {
                            const uint32_t bf[2] = { bh[ng][hf * 2], bh[ng][hf * 2 + 1] };
                            mma_bf16(acc[mt][ng * 2 + hf], al[mt], bf);
                        }
            }
        }

        if (++stage == GSTAGES) stage = 0;
    }

    const int g  = lid >> 2;
    const int tg = (lid & 3) * 2;

    if (mode == 0) {
        #pragma unroll
        for (int mt = 0; mt < 4; mt++) {
            #pragma unroll
            for (int nt = 0; nt < 4; nt++) {
                const int mrow = m0 + Wm + mt * 16 + g;
                const int ncol = n0 + Wn + nt * 8 + tg;
                float2 v0 = make_float2(acc[mt][nt][0], acc[mt][nt][1]);
                float2 v1 = make_float2(acc[mt][nt][2], acc[mt][nt][3]);
                *(float2*)(C + (size_t)mrow * N + ncol)       = v0;
                *(float2*)(C + (size_t)(mrow + 8) * N + ncol) = v1;
            }
        }
    } else {
        // QKV mode: Q cols [0,1024): scaled split -> oqh/oql
        //           K cols [1024,2048): split -> okh/okl
        //           V cols [2048,3072): fp32 -> C (stride QKVROW)
        #pragma unroll
        for (int mt = 0; mt < 4; mt++) {
            #pragma unroll
            for (int nt = 0; nt < 4; nt++) {
                const int mrow = m0 + Wm + mt * 16 + g;
                const int ncol = n0 + Wn + nt * 8 + tg;
                #pragma unroll
                for (int rr = 0; rr < 2; rr++) {
                    const int mr = mrow + rr * 8;
                    float v0 = acc[mt][nt][rr * 2 + 0];
                    float v1 = acc[mt][nt][rr * 2 + 1];
                    if (ncol < DMODEL) {
                        uint32_t hi, lo;
                        split2(v0 * QSCALE, v1 * QSCALE, hi, lo);
                        *(uint32_t*)(oqh + (size_t)mr * DMODEL + ncol) = hi;
                        *(uint32_t*)(oql + (size_t)mr * DMODEL + ncol) = lo;
                    } else if (ncol < 2 * DMODEL) {
                        uint32_t hi, lo;
                        split2(v0, v1, hi, lo);
                        const int nc = ncol - DMODEL;
                        *(uint32_t*)(okh + (size_t)mr * DMODEL + nc) = hi;
                        *(uint32_t*)(okl + (size_t)mr * DMODEL + nc) = lo;
                    } else {
                        *(float2*)(C + (size_t)mr * QKVROW + ncol) =
                            make_float2(v0, v1);
                    }
                }
            }
        }
    }
}

// ---------------------------------------------------------------------------
// Prepass: V -> transposed [b,h,d,T] bf16 hi/lo.
// ---------------------------------------------------------------------------
__global__ void __launch_bounds__(256) v_split_T_kernel(
    const float* __restrict__ qkv,
    __nv_bfloat16* __restrict__ vthp, __nv_bfloat16* __restrict__ vtlp)
{
    __shared__ float t[32][33];
    const int tx = threadIdx.x;
    const int ty = threadIdx.y;
    const int bh = blockIdx.z;
    const int b  = bh >> 4;
    const int h  = bh & 15;
    const int d0 = blockIdx.y * 32;
    const int t0 = blockIdx.x * 32;

    const size_t col = 2 * DMODEL + h * HD + d0 + tx;
    #pragma unroll
    for (int j = 0; j < 32; j += 8)
        t[ty + j][tx] = qkv[(size_t)(b * SEQ + t0 + ty + j) * QKVROW + col];
    __syncthreads();
    #pragma unroll
    for (int j = 0; j < 32; j += 8) {
        const float v = t[tx][ty + j];
        __nv_bfloat16 hi = __float2bfloat16_rn(v);
        __nv_bfloat16 lo = __float2bfloat16_rn(v - __bfloat162float(hi));
        const size_t o = (size_t)(bh * HD + d0 + ty + j) * SEQ + t0 + tx;
        vthp[o] = hi;
        vtlp[o] = lo;
    }
}

// ---------------------------------------------------------------------------
// Flash attention via mma.sync bf16 3-term. 3-stage pipeline (R9).
// ---------------------------------------------------------------------------
#define KSTR       144
#define REGION     (64 * KSTR)
#define ABUF       (4 * REGION)
#define ATT_STAGES 3
#define ATT_SMEM   (ATT_STAGES * ABUF)  // 110592

__global__ void __launch_bounds__(256) attn_mma_kernel(
    const __nv_bfloat16* __restrict__ qh, const __nv_bfloat16* __restrict__ ql,
    const __nv_bfloat16* __restrict__ kh, const __nv_bfloat16* __restrict__ kl,
    const __nv_bfloat16* __restrict__ vth, const __nv_bfloat16* __restrict__ vtl,
    __nv_bfloat16* __restrict__ yh, __nv_bfloat16* __restrict__ yl)
{
    extern __shared__ __align__(16) char asm_[];

    const int tid = threadIdx.x;
    const int wid = tid >> 5;
    const int lid = tid & 31;
    const int qt = gridDim.x - 1 - blockIdx.x;
    const int h  = blockIdx.y;
    const int b  = blockIdx.z;
    const int q0 = qt * 128;
    const int NT = 2 * (qt + 1);

    const uint32_t sb = smem_u32(asm_);

    const int g  = lid >> 2;
    const int c2 = (lid & 3) * 2;
    const int bl8 = lid & 7;
    const int bkh = (lid >> 3) & 1;
    const int bnh = lid >> 4;

    uint32_t aqh[4][4], aql[4][4];
    {
        const size_t r0 = (size_t)(b * SEQ + q0 + wid * 16 + g) * DMODEL + h * HD;
        const size_t r1 = r0 + 8 * DMODEL;
        #pragma unroll
        for (int ks = 0; ks < 4; ks++) {
            const int k0 = ks * 16 + c2;
            aqh[ks][0] = ld32(qh + r0 + k0);
            aqh[ks][1] = ld32(qh + r1 + k0);
            aqh[ks][2] = ld32(qh + r0 + k0 + 8);
            aqh[ks][3] = ld32(qh + r1 + k0 + 8);
            aql[ks][0] = ld32(ql + r0 + k0);
            aql[ks][1] = ld32(ql + r1 + k0);
            aql[ks][2] = ld32(ql + r0 + k0 + 8);
            aql[ks][3] = ld32(ql + r1 + k0 + 8);
        }
    }

    const size_t kbase = (size_t)(b * SEQ) * DMODEL + h * HD;
    const size_t vbase = (size_t)((b * NHEAD + h) * HD) * SEQ;

    auto load_tile = [&](int stage, int kt) {
        const uint32_t buf = sb + (uint32_t)stage * ABUF;
        const int ch = tid & 7;
        const int rr = tid >> 3;
        #pragma unroll
        for (int p = 0; p < 8; p++) {
            const int region = p >> 1;
            const int row = ((p & 1) << 5) + rr;
            const uint32_t dst = buf + region * REGION + row * KSTR + ch * 16;
            const __nv_bfloat16* src;
            if (region == 0)
                src = kh + kbase + (size_t)(kt * 64 + row) * DMODEL + ch * 8;
            else if (region == 1)
                src = kl + kbase + (size_t)(kt * 64 + row) * DMODEL + ch * 8;
            else if (region == 2)
                src = vth + vbase + (size_t)row * SEQ + kt * 64 + ch * 8;
            else
                src = vtl + vbase + (size_t)row * SEQ + kt * 64 + ch * 8;
            cp16(dst, src);
        }
        CP_COMMIT();
    };

    float O[8][4];
    #pragma unroll
    for (int nt = 0; nt < 8; nt++)
        #pragma unroll
        for (int c = 0; c < 4; c++) O[nt][c] = 0.0f;
    float m0 = -INFINITY, m1 = -INFINITY, l0 = 0.0f, l1 = 0.0f;

    load_tile(0, 0);
    if (NT > 1) load_tile(1, 1);

    int stage = 0;
    for (int kt = 0; kt < NT; kt++) {
        if (kt + 1 < NT) { CP_WAIT1(); } else { CP_WAIT0(); }
        __syncthreads();

        if (kt + 2 < NT) {
            int ns = stage + 2; if (ns >= ATT_STAGES) ns -= ATT_STAGES;
            load_tile(ns, kt + 2);
        }

        const uint32_t buf = sb + (uint32_t)stage * ABUF;

        float S[8][4];
        #pragma unroll
        for (int nt = 0; nt < 8; nt++)
            #pragma unroll
            for (int c = 0; c < 4; c++) S[nt][c] = 0.0f;

        #pragma unroll
        for (int ks = 0; ks < 4; ks++) {
            const uint32_t koff = (uint32_t)(ks * 16 + bkh * 8) * 2;
            #pragma unroll
            for (int ng = 0; ng < 4; ng++) {
                const uint32_t row = (uint32_t)(ng * 16 + bl8 + bnh * 8) * KSTR + koff;
                uint32_t kbh[4], kbl[4];
                ldsm4(kbh, buf + 0 * REGION + row);
                ldsm4(kbl, buf + 1 * REGION + row);
                #pragma unroll
                for (int hf = 0; hf < 2; hf++) {
                    float* c = S[ng * 2 + hf];
                    const uint32_t b1[2] = { kbh[hf * 2], kbh[hf * 2 + 1] };
                    const uint32_t b2[2] = { kbl[hf * 2], kbl[hf * 2 + 1] };
                    mma_bf16(c, aqh[ks], b1);
                    mma_bf16(c, aqh[ks], b2);
                    mma_bf16(c, aql[ks], b1);
                }
            }
        }

        if (kt >= 2 * qt) {
            const int qr0 = q0 + wid * 16 + g;
            #pragma unroll
            for (int nt = 0; nt < 8; nt++) {
                #pragma unroll
                for (int e = 0; e < 2; e++) {
                    const int key = kt * 64 + nt * 8 + c2 + e;
                    if (key > qr0)     S[nt][e]     = -INFINITY;
                    if (key > qr0 + 8) S[nt][2 + e] = -INFINITY;
                }
            }
        }

        float mx0 = -INFINITY, mx1 = -INFINITY;
        #pragma unroll
        for (int nt = 0; nt < 8; nt++) {
            mx0 = fmaxf(mx0, fmaxf(S[nt][0], S[nt][1]));
            mx1 = fmaxf(mx1, fmaxf(S[nt][2], S[nt][3]));
        }
        #pragma unroll
        for (int off = 1; off <= 2; off <<= 1) {
            mx0 = fmaxf(mx0, __shfl_xor_sync(0xffffffffu, mx0, off));
            mx1 = fmaxf(mx1, __shfl_xor_sync(0xffffffffu, mx1, off));
        }
        const float mn0 = fmaxf(m0, mx0);
        const float mn1 = fmaxf(m1, mx1);
        const float a0 = exp2f(m0 - mn0);
        const float a1 = exp2f(m1 - mn1);
        m0 = mn0; m1 = mn1;

        float rs0 = 0.0f, rs1 = 0.0f;
        #pragma unroll
        for (int nt = 0; nt < 8; nt++) {
            S[nt][0] = exp2f(S[nt][0] - m0);
            S[nt][1] = exp2f(S[nt][1] - m0);
            S[nt][2] = exp2f(S[nt][2] - m1);
            S[nt][3] = exp2f(S[nt][3] - m1);
            rs0 += S[nt][0] + S[nt][1];
            rs1 += S[nt][2] + S[nt][3];
        }
        #pragma unroll
        for (int off = 1; off <= 2; off <<= 1) {
            rs0 += __shfl_xor_sync(0xffffffffu, rs0, off);
            rs1 += __shfl_xor_sync(0xffffffffu, rs1, off);
        }
        l0 = l0 * a0 + rs0;
        l1 = l1 * a1 + rs1;

        #pragma unroll
        for (int nt = 0; nt < 8; nt++) {
            O[nt][0] *= a0; O[nt][1] *= a0;
            O[nt][2] *= a1; O[nt][3] *= a1;
        }

        uint32_t ph[4][4], pl[4][4];
        #pragma unroll
        for (int ks = 0; ks < 4; ks++) {
            #pragma unroll
            for (int r = 0; r < 4; r++) {
                const int nt = ks * 2 + (r >> 1);
                const float p0 = S[nt][(r & 1) * 2 + 0];
                const float p1 = S[nt][(r & 1) * 2 + 1];
                __nv_bfloat16 h0 = __float2bfloat16_rn(p0);
                __nv_bfloat16 h1 = __float2bfloat16_rn(p1);
                __nv_bfloat16 e0 = __float2bfloat16_rn(p0 - __bfloat162float(h0));
                __nv_bfloat16 e1 = __float2bfloat16_rn(p1 - __bfloat162float(h1));
                ph[ks][r] = packbf(h0, h1);
                pl[ks][r] = packbf(e0, e1);
            }
        }

        #pragma unroll
        for (int ks = 0; ks < 4; ks++) {
            const uint32_t koff = (uint32_t)(ks * 16 + bkh * 8) * 2;
            #pragma unroll
            for (int ng = 0; ng < 4; ng++) {
                const uint32_t row = (uint32_t)(ng * 16 + bl8 + bnh * 8) * KSTR + koff;
                uint32_t vbh[4], vbl[4];
                ldsm4(vbh, buf + 2 * REGION + row);
                ldsm4(vbl, buf + 3 * REGION + row);
                #pragma unroll
                for (int hf = 0; hf < 2; hf++) {
                    float* c = O[ng * 2 + hf];
                    const uint32_t b1[2] = { vbh[hf * 2], vbh[hf * 2 + 1] };
                    const uint32_t b2[2] = { vbl[hf * 2], vbl[hf * 2 + 1] };
                    mma_bf16(c, ph[ks], b1);
                    mma_bf16(c, ph[ks], b2);
                    mma_bf16(c, pl[ks], b1);
                }
            }
        }

        if (++stage == ATT_STAGES) stage = 0;
    }

    const float inv0 = 1.0f / l0;
    const float inv1 = 1.0f / l1;
    const size_t o0 = (size_t)(b * SEQ + q0 + wid * 16 + g) * DMODEL + h * HD;
    const size_t o1 = o0 + 8 * DMODEL;
    #pragma unroll
    for (int nt = 0; nt < 8; nt++) {
        uint32_t hi, lo;
        split2(O[nt][0] * inv0, O[nt][1] * inv0, hi, lo);
        *(uint32_t*)(yh + o0 + nt * 8 + c2) = hi;
        *(uint32_t*)(yl + o0 + nt * 8 + c2) = lo;
        split2(O[nt][2] * inv1, O[nt][3] * inv1, hi, lo);
        *(uint32_t*)(yh + o1 + nt * 8 + c2) = hi;
        *(uint32_t*)(yl + o1 + nt * 8 + c2) = lo;
    }
}

// ---------------------------------------------------------------------------
// Launch
// ---------------------------------------------------------------------------
extern "C" void kernel_launch(void* const* d_in, const int* in_sizes, int n_in,
                              void* d_out, int out_size)
{
    const float* x      = (const float*)d_in[0];
    const float* W_attn = (const float*)d_in[1];
    const float* W_proj = (const float*)d_in[2];
    float* out = (float*)d_out;

    void *p_qkv, *p_xh, *p_xl, *p_yh, *p_yl, *p_wah, *p_wal, *p_wph, *p_wpl;
    void *p_qh, *p_ql, *p_kh, *p_kl, *p_vh, *p_vl;
    cudaGetSymbolAddress(&p_qkv, g_qkv);
    cudaGetSymbolAddress(&p_xh, g_xh);
    cudaGetSymbolAddress(&p_xl, g_xl);
    cudaGetSymbolAddress(&p_yh, g_yh);
    cudaGetSymbolAddress(&p_yl, g_yl);
    cudaGetSymbolAddress(&p_wah, g_wah);
    cudaGetSymbolAddress(&p_wal, g_wal);
    cudaGetSymbolAddress(&p_wph, g_wph);
    cudaGetSymbolAddress(&p_wpl, g_wpl);
    cudaGetSymbolAddress(&p_qh, g_qh);
    cudaGetSymbolAddress(&p_ql, g_ql);
    cudaGetSymbolAddress(&p_kh, g_kh);
    cudaGetSymbolAddress(&p_kl, g_kl);
    cudaGetSymbolAddress(&p_vh, g_vth);
    cudaGetSymbolAddress(&p_vl, g_vtl);
    float* qkv = (float*)p_qkv;
    __nv_bfloat16* xh = (__nv_bfloat16*)p_xh;
    __nv_bfloat16* xl = (__nv_bfloat16*)p_xl;
    __nv_bfloat16* yh = (__nv_bfloat16*)p_yh;
    __nv_bfloat16* yl = (__nv_bfloat16*)p_yl;
    __nv_bfloat16* wah = (__nv_bfloat16*)p_wah;
    __nv_bfloat16* wal = (__nv_bfloat16*)p_wal;
    __nv_bfloat16* wph = (__nv_bfloat16*)p_wph;
    __nv_bfloat16* wpl = (__nv_bfloat16*)p_wpl;
    __nv_bfloat16* qh = (__nv_bfloat16*)p_qh;
    __nv_bfloat16* ql = (__nv_bfloat16*)p_ql;
    __nv_bfloat16* kh = (__nv_bfloat16*)p_kh;
    __nv_bfloat16* kl = (__nv_bfloat16*)p_kl;
    __nv_bfloat16* vth = (__nv_bfloat16*)p_vh;
    __nv_bfloat16* vtl = (__nv_bfloat16*)p_vl;

    cudaFuncSetAttribute(tc_gemm_bf16,
                         cudaFuncAttributeMaxDynamicSharedMemorySize, SMEM_DYN);
    cudaFuncSetAttribute(attn_mma_kernel,
                         cudaFuncAttributeMaxDynamicSharedMemorySize, ATT_SMEM);

    // 0) prepasses
    split_kernel<<<(NTOK * DMODEL / 4) / 256, 256>>>(x, xh, xl);
    {
        dim3 blk(32, 8);
        transpose_split_kernel<<<dim3(QKVROW / 32, DMODEL / 32), blk>>>(
            W_attn, wah, wal, DMODEL, QKVROW);
        transpose_split_kernel<<<dim3(DMODEL / 32, DMODEL / 32), blk>>>(
            W_proj, wph, wpl, DMODEL, DMODEL);
    }

    // 1) qkv = x @ W_attn (mode 1: Q/K split written directly, V fp32)
    {
        dim3 grid(QKVROW / 128, NTOK / 128);
        tc_gemm_bf16<<<grid, 256, SMEM_DYN>>>(xh, xl, wah, wal, qkv,
                                              NTOK, QKVROW, DMODEL, 1,
                                              qh, ql, kh, kl);
    }

    // 2) split+transpose V
    {
        dim3 blk(32, 8);
        v_split_T_kernel<<<dim3(SEQ / 32, HD / 32, BATCH * NHEAD), blk>>>(qkv, vth, vtl);
    }

    // 3) attention -> y (bf16 hi/lo)
    {
        dim3 grid(SEQ / 128, NHEAD, BATCH);
        attn_mma_kernel<<<grid, 256, ATT_SMEM>>>(qh, ql, kh, kl, vth, vtl, yh, yl);
    }

    // 4) out = y @ W_proj (mode 0: plain fp32)
    {
        dim3 grid(DMODEL / 128, NTOK / 128);
        tc_gemm_bf16<<<grid, 256, SMEM_DYN>>>(yh, yl, wph, wpl, out,
                                              NTOK, DMODEL, DMODEL, 0,
                                              nullptr, nullptr, nullptr, nullptr);
    }
}

// round 17
// speedup vs baseline: 1.9398x; 1.0379x over previous
#include <cuda_runtime.h>
#include <cuda_bf16.h>
#include <math.h>
#include <stdint.h>

// Problem constants
#define DMODEL 1024
#define NHEAD  16
#define HD     64
#define BATCH  4
#define SEQ    2048
#define NTOK   (BATCH * SEQ)          // 8192
#define QKVROW (3 * DMODEL)           // 3072

// Scratch (device globals: allocation-guard safe)
__device__ float g_qkv[(size_t)NTOK * QKVROW];   // only V region used now
__device__ __nv_bfloat16 g_xh[(size_t)NTOK * DMODEL];
__device__ __nv_bfloat16 g_xl[(size_t)NTOK * DMODEL];
__device__ __nv_bfloat16 g_yh[(size_t)NTOK * DMODEL];
__device__ __nv_bfloat16 g_yl[(size_t)NTOK * DMODEL];
__device__ __nv_bfloat16 g_wah[(size_t)QKVROW * DMODEL];
__device__ __nv_bfloat16 g_wal[(size_t)QKVROW * DMODEL];
__device__ __nv_bfloat16 g_wph[(size_t)DMODEL * DMODEL];
__device__ __nv_bfloat16 g_wpl[(size_t)DMODEL * DMODEL];
__device__ __nv_bfloat16 g_qh[(size_t)NTOK * DMODEL];
__device__ __nv_bfloat16 g_ql[(size_t)NTOK * DMODEL];
__device__ __nv_bfloat16 g_kh[(size_t)NTOK * DMODEL];
__device__ __nv_bfloat16 g_kl[(size_t)NTOK * DMODEL];
__device__ __nv_bfloat16 g_vth[(size_t)BATCH * NHEAD * HD * SEQ]; // [b,h,d,T]
__device__ __nv_bfloat16 g_vtl[(size_t)BATCH * NHEAD * HD * SEQ];

#define QSCALE (0.125f * 1.44269504088896f)

// ---------------------------------------------------------------------------
// PTX helpers
// ---------------------------------------------------------------------------
__device__ __forceinline__ uint32_t smem_u32(const void* p) {
    uint32_t a;
    asm("{ .reg .u64 t; cvta.to.shared.u64 t, %1; cvt.u32.u64 %0, t; }"
        : "=r"(a) : "l"(p));
    return a;
}

__device__ __forceinline__ void ldsm4(uint32_t* r, uint32_t addr) {
    asm volatile("ldmatrix.sync.aligned.m8n8.x4.shared.b16 {%0,%1,%2,%3}, [%4];"
        : "=r"(r[0]), "=r"(r[1]), "=r"(r[2]), "=r"(r[3]) : "r"(addr));
}

__device__ __forceinline__ void mma_bf16(float* c, const uint32_t* a,
                                         const uint32_t* b) {
    asm volatile(
        "mma.sync.aligned.m16n8k16.row.col.f32.bf16.bf16.f32 "
        "{%0,%1,%2,%3}, {%4,%5,%6,%7}, {%8,%9}, {%0,%1,%2,%3};"
        : "+f"(c[0]), "+f"(c[1]), "+f"(c[2]), "+f"(c[3])
        : "r"(a[0]), "r"(a[1]), "r"(a[2]), "r"(a[3]), "r"(b[0]), "r"(b[1]));
}

__device__ __forceinline__ void cp16(uint32_t dst, const void* src) {
    asm volatile("cp.async.cg.shared.global [%0], [%1], 16;"
        :: "r"(dst), "l"(src));
}
#define CP_COMMIT() asm volatile("cp.async.commit_group;" ::: "memory")
#define CP_WAIT1()  asm volatile("cp.async.wait_group 1;" ::: "memory")
#define CP_WAIT0()  asm volatile("cp.async.wait_group 0;" ::: "memory")

__device__ __forceinline__ uint32_t packbf(__nv_bfloat16 a, __nv_bfloat16 b) {
    __nv_bfloat162 t = __halves2bfloat162(a, b);
    return *(uint32_t*)&t;
}

__device__ __forceinline__ void split4(float4 v, uint2& hi, uint2& lo) {
    __nv_bfloat16 hx = __float2bfloat16_rn(v.x);
    __nv_bfloat16 hy = __float2bfloat16_rn(v.y);
    __nv_bfloat16 hz = __float2bfloat16_rn(v.z);
    __nv_bfloat16 hw = __float2bfloat16_rn(v.w);
    __nv_bfloat16 lx = __float2bfloat16_rn(v.x - __bfloat162float(hx));
    __nv_bfloat16 ly = __float2bfloat16_rn(v.y - __bfloat162float(hy));
    __nv_bfloat16 lz = __float2bfloat16_rn(v.z - __bfloat162float(hz));
    __nv_bfloat16 lw = __float2bfloat16_rn(v.w - __bfloat162float(hw));
    hi.x = packbf(hx, hy); hi.y = packbf(hz, hw);
    lo.x = packbf(lx, ly); lo.y = packbf(lz, lw);
}

__device__ __forceinline__ void split2(float a, float b,
                                       uint32_t& hi, uint32_t& lo) {
    __nv_bfloat16 ha = __float2bfloat16_rn(a);
    __nv_bfloat16 hb = __float2bfloat16_rn(b);
    hi = packbf(ha, hb);
    lo = packbf(__float2bfloat16_rn(a - __bfloat162float(ha)),
                __float2bfloat16_rn(b - __bfloat162float(hb)));
}

__device__ __forceinline__ uint32_t ld32(const __nv_bfloat16* p) {
    return *(const uint32_t*)p;
}

// ---------------------------------------------------------------------------
// Prepass: elementwise split fp32 -> bf16 hi/lo
// ---------------------------------------------------------------------------
__global__ void __launch_bounds__(256) split_kernel(
    const float* __restrict__ A,
    __nv_bfloat16* __restrict__ Ah, __nv_bfloat16* __restrict__ Al)
{
    const size_t i4 = ((size_t)blockIdx.x * 256 + threadIdx.x) * 4;
    float4 v = *(const float4*)(A + i4);
    uint2 hi, lo;
    split4(v, hi, lo);
    *(uint2*)(Ah + i4) = hi;
    *(uint2*)(Al + i4) = lo;
}

// ---------------------------------------------------------------------------
// Prepass: fused transpose + split.
// ---------------------------------------------------------------------------
__global__ void __launch_bounds__(256) transpose_split_kernel(
    const float* __restrict__ W,
    __nv_bfloat16* __restrict__ Wth, __nv_bfloat16* __restrict__ Wtl,
    int K, int N)
{
    __shared__ float t[32][33];
    const int tx = threadIdx.x;
    const int ty = threadIdx.y;
    const int n0 = blockIdx.x * 32;
    const int k0 = blockIdx.y * 32;
    #pragma unroll
    for (int j = 0; j < 32; j += 8)
        t[ty + j][tx] = W[(size_t)(k0 + ty + j) * N + n0 + tx];
    __syncthreads();
    #pragma unroll
    for (int j = 0; j < 32; j += 8) {
        const float v = t[tx][ty + j];
        __nv_bfloat16 hi = __float2bfloat16_rn(v);
        __nv_bfloat16 lo = __float2bfloat16_rn(v - __bfloat162float(hi));
        const size_t o = (size_t)(n0 + ty + j) * K + k0 + tx;
        Wth[o] = hi;
        Wtl[o] = lo;
    }
}

// ---------------------------------------------------------------------------
// bf16 GEMM (3-term), 128x128 tile, BK=32, 3-stage pipeline (R8 schedule).
// mode=1 epilogue writes Q/K as split bf16 (+QSCALE on Q), V as fp32.
// ---------------------------------------------------------------------------
#define GROWB    128
#define GREGA    (128 * GROWB)
#define GBUF     (2 * GREGA)          // 32768 per stage
#define GSTAGES  3
#define SMEM_DYN (GSTAGES * GBUF)     // 98304

__global__ void __launch_bounds__(256, 2) tc_gemm_bf16(
    const __nv_bfloat16* __restrict__ Ah, const __nv_bfloat16* __restrict__ Al,
    const __nv_bfloat16* __restrict__ Bh, const __nv_bfloat16* __restrict__ Bl,
    float* __restrict__ C, int M, int N, int K, int mode,
    __nv_bfloat16* __restrict__ oqh, __nv_bfloat16* __restrict__ oql,
    __nv_bfloat16* __restrict__ okh, __nv_bfloat16* __restrict__ okl)
{
    extern __shared__ __align__(16) char dsm[];

    const int tid = threadIdx.x;
    const int wid = tid >> 5;
    const int lid = tid & 31;
    const int m0 = blockIdx.y * 128;
    const int n0 = blockIdx.x * 128;

    const int Wm = (wid >> 2) * 64;
    const int Wn = (wid & 3) * 32;

    const uint32_t sb = smem_u32(dsm);

    const int l16 = lid & 15;
    const int kh  = lid >> 4;
    const int bl8 = lid & 7;
    const int bkh = (lid >> 3) & 1;
    const int bnh = lid >> 4;

    const int lrow = tid >> 3;
    const int lc   = tid & 7;

    auto load_tile = [&](int stage, int k0) {
        const uint32_t buf = sb + (uint32_t)stage * GBUF;
        #pragma unroll
        for (int p = 0; p < 8; p++) {
            const int region = p >> 2;
            const int row = ((p & 3) << 5) + lrow;
            const uint32_t dst = buf + region * GREGA + row * GROWB
                               + ((lc ^ (row & 7)) << 4);
            const __nv_bfloat16* src;
            if (region == 0)
                src = (lc < 4 ? Ah + (size_t)(m0 + row) * K + k0 + lc * 8
                              : Al + (size_t)(m0 + row) * K + k0 + (lc - 4) * 8);
            else
                src = (lc < 4 ? Bh + (size_t)(n0 + row) * K + k0 + lc * 8
                              : Bl + (size_t)(n0 + row) * K + k0 + (lc - 4) * 8);
            cp16(dst, src);
        }
        CP_COMMIT();
    };

    float acc[4][4][4];
    #pragma unroll
    for (int i = 0; i < 4; i++)
        #pragma unroll
        for (int j = 0; j < 4; j++)
            #pragma unroll
            for (int c = 0; c < 4; c++) acc[i][j][c] = 0.0f;

    const int NIT = K >> 5;
    load_tile(0, 0);
    if (NIT > 1) load_tile(1, 32);

    int stage = 0;
    for (int it = 0; it < NIT; it++) {
        if (it + 1 < NIT) { CP_WAIT1(); } else { CP_WAIT0(); }
        __syncthreads();

        if (it + 2 < NIT) {
            int ns = stage + 2; if (ns >= GSTAGES) ns -= GSTAGES;
            load_tile(ns, (it + 2) * 32);
        }

        const uint32_t bufA = sb + (uint32_t)stage * GBUF;
        const uint32_t bufB = bufA + GREGA;

        #pragma unroll
        for (int ks = 0; ks < 2; ks++) {
            uint32_t ah[4][4], al[4][4];
            #pragma unroll
            for (int mt = 0; mt < 4; mt++) {
                const int row = Wm + mt * 16 + l16;
                const uint32_t rb = bufA + (uint32_t)row * GROWB;
                const int r7 = row & 7;
                ldsm4(ah[mt], rb + (uint32_t)(((2 * ks + kh)     ^ r7) << 4));
                ldsm4(al[mt], rb + (uint32_t)(((4 + 2 * ks + kh) ^ r7) << 4));
            }
            uint32_t bh[2][4], bl[2][4];
            #pragma unroll
            for (int ng = 0; ng < 2; ng++) {
                const int row = Wn + ng * 16 + bl8 + bnh * 8;
                const uint32_t rb = bufB + (uint32_t)row * GROWB;
                const int r7 = row & 7;
                ldsm4(bh[ng], rb + (uint32_t)(((2 * ks + bkh)     ^ r7) << 4));
                ldsm4(bl[ng], rb + (uint32_t)(((4 + 2 * ks + bkh) ^ r7) << 4));
            }

            #pragma unroll
            for (int term = 0; term < 3; term++) {
                #pragma unroll
                for (int mt = 0; mt < 4; mt++)
                    #pragma unroll
                    for (int ng = 0; ng < 2; ng++)
                        #pragma unroll
                        for (int hf = 0; hf < 2; hf++) {
                            float* c = acc[mt][ng * 2 + hf];
                            const uint32_t* af = (term == 2) ? al[mt] : ah[mt];
                            const uint32_t* bsrc = (term == 1) ? bl[ng] : bh[ng];
                            const uint32_t bf[2] = { bsrc[hf * 2], bsrc[hf * 2 + 1] };
                            mma_bf16(c, af, bf);
                        }
            }
        }

        if (++stage == GSTAGES) stage = 0;
    }

    const int g  = lid >> 2;
    const int tg = (lid & 3) * 2;

    if (mode == 0) {
        #pragma unroll
        for (int mt = 0; mt < 4; mt++) {
            #pragma unroll
            for (int nt = 0; nt < 4; nt++) {
                const int mrow = m0 + Wm + mt * 16 + g;
                const int ncol = n0 + Wn + nt * 8 + tg;
                float2 v0 = make_float2(acc[mt][nt][0], acc[mt][nt][1]);
                float2 v1 = make_float2(acc[mt][nt][2], acc[mt][nt][3]);
                *(float2*)(C + (size_t)mrow * N + ncol)       = v0;
                *(float2*)(C + (size_t)(mrow + 8) * N + ncol) = v1;
            }
        }
    } else {
        #pragma unroll
        for (int mt = 0; mt < 4; mt++) {
            #pragma unroll
            for (int nt = 0; nt < 4; nt++) {
                const int mrow = m0 + Wm + mt * 16 + g;
                const int ncol = n0 + Wn + nt * 8 + tg;
                #pragma unroll
                for (int rr = 0; rr < 2; rr++) {
                    const int mr = mrow + rr * 8;
                    float v0 = acc[mt][nt][rr * 2 + 0];
                    float v1 = acc[mt][nt][rr * 2 + 1];
                    if (ncol < DMODEL) {
                        uint32_t hi, lo;
                        split2(v0 * QSCALE, v1 * QSCALE, hi, lo);
                        *(uint32_t*)(oqh + (size_t)mr * DMODEL + ncol) = hi;
                        *(uint32_t*)(oql + (size_t)mr * DMODEL + ncol) = lo;
                    } else if (ncol < 2 * DMODEL) {
                        uint32_t hi, lo;
                        split2(v0, v1, hi, lo);
                        const int nc = ncol - DMODEL;
                        *(uint32_t*)(okh + (size_t)mr * DMODEL + nc) = hi;
                        *(uint32_t*)(okl + (size_t)mr * DMODEL + nc) = lo;
                    } else {
                        *(float2*)(C + (size_t)mr * QKVROW + ncol) =
                            make_float2(v0, v1);
                    }
                }
            }
        }
    }
}

// ---------------------------------------------------------------------------
// Prepass: V -> transposed [b,h,d,T] bf16 hi/lo.
// ---------------------------------------------------------------------------
__global__ void __launch_bounds__(256) v_split_T_kernel(
    const float* __restrict__ qkv,
    __nv_bfloat16* __restrict__ vthp, __nv_bfloat16* __restrict__ vtlp)
{
    __shared__ float t[32][33];
    const int tx = threadIdx.x;
    const int ty = threadIdx.y;
    const int bh = blockIdx.z;
    const int b  = bh >> 4;
    const int h  = bh & 15;
    const int d0 = blockIdx.y * 32;
    const int t0 = blockIdx.x * 32;

    const size_t col = 2 * DMODEL + h * HD + d0 + tx;
    #pragma unroll
    for (int j = 0; j < 32; j += 8)
        t[ty + j][tx] = qkv[(size_t)(b * SEQ + t0 + ty + j) * QKVROW + col];
    __syncthreads();
    #pragma unroll
    for (int j = 0; j < 32; j += 8) {
        const float v = t[tx][ty + j];
        __nv_bfloat16 hi = __float2bfloat16_rn(v);
        __nv_bfloat16 lo = __float2bfloat16_rn(v - __bfloat162float(hi));
        const size_t o = (size_t)(bh * HD + d0 + ty + j) * SEQ + t0 + tx;
        vthp[o] = hi;
        vtlp[o] = lo;
    }
}

// ---------------------------------------------------------------------------
// Flash attention via mma.sync bf16 3-term.
// R11: Q hi/lo in SMEM (ldmatrix per ks) -> regs <= 128 -> 2 CTAs/SM.
// 2-stage KV pipeline (2 barriers/tile; cross-CTA overlap hides them).
// SMEM: QH 18432 | QL 18432 | stage0 36864 | stage1 36864 = 110592.
// ---------------------------------------------------------------------------
#define KSTR       144
#define QREG       (128 * KSTR)        // 18432 per Q region
#define REGION     (64 * KSTR)
#define ABUF       (4 * REGION)        // 36864 per KV stage
#define ATT_SMEM   (2 * QREG + 2 * ABUF)  // 110592

__global__ void __launch_bounds__(256, 2) attn_mma_kernel(
    const __nv_bfloat16* __restrict__ qh, const __nv_bfloat16* __restrict__ ql,
    const __nv_bfloat16* __restrict__ kh, const __nv_bfloat16* __restrict__ kl,
    const __nv_bfloat16* __restrict__ vth, const __nv_bfloat16* __restrict__ vtl,
    __nv_bfloat16* __restrict__ yh, __nv_bfloat16* __restrict__ yl)
{
    extern __shared__ __align__(16) char asm_[];

    const int tid = threadIdx.x;
    const int wid = tid >> 5;
    const int lid = tid & 31;
    const int qt = gridDim.x - 1 - blockIdx.x;
    const int h  = blockIdx.y;
    const int b  = blockIdx.z;
    const int q0 = qt * 128;
    const int NT = 2 * (qt + 1);

    const uint32_t sb  = smem_u32(asm_);
    const uint32_t kvb = sb + 2 * QREG;

    const int g  = lid >> 2;
    const int c2 = (lid & 3) * 2;
    const int l16 = lid & 15;
    const int akh = lid >> 4;          // A-frag k-half
    const int bl8 = lid & 7;
    const int bkh = (lid >> 3) & 1;
    const int bnh = lid >> 4;

    const size_t qgbase = (size_t)(b * SEQ + q0) * DMODEL + h * HD;
    const size_t kbase  = (size_t)(b * SEQ) * DMODEL + h * HD;
    const size_t vbase  = (size_t)((b * NHEAD + h) * HD) * SEQ;

    // ---- Q -> SMEM (own cp.async group) ----
    {
        const int ch = tid & 7;
        const int rr = tid >> 3;
        #pragma unroll
        for (int p = 0; p < 8; p++) {
            const int region = p >> 2;               // 0=QH, 1=QL
            const int row = ((p & 3) << 5) + rr;     // 0..127
            const uint32_t dst = sb + region * QREG + row * KSTR + ch * 16;
            const __nv_bfloat16* src = (region == 0)
                ? qh + qgbase + (size_t)row * DMODEL + ch * 8
                : ql + qgbase + (size_t)row * DMODEL + ch * 8;
            cp16(dst, src);
        }
        CP_COMMIT();
    }

    auto load_tile = [&](int stage, int kt) {
        const uint32_t buf = kvb + (uint32_t)stage * ABUF;
        const int ch = tid & 7;
        const int rr = tid >> 3;
        #pragma unroll
        for (int p = 0; p < 8; p++) {
            const int region = p >> 1;
            const int row = ((p & 1) << 5) + rr;
            const uint32_t dst = buf + region * REGION + row * KSTR + ch * 16;
            const __nv_bfloat16* src;
            if (region == 0)
                src = kh + kbase + (size_t)(kt * 64 + row) * DMODEL + ch * 8;
            else if (region == 1)
                src = kl + kbase + (size_t)(kt * 64 + row) * DMODEL + ch * 8;
            else if (region == 2)
                src = vth + vbase + (size_t)row * SEQ + kt * 64 + ch * 8;
            else
                src = vtl + vbase + (size_t)row * SEQ + kt * 64 + ch * 8;
            cp16(dst, src);
        }
        CP_COMMIT();
    };

    float O[8][4];
    #pragma unroll
    for (int nt = 0; nt < 8; nt++)
        #pragma unroll
        for (int c = 0; c < 4; c++) O[nt][c] = 0.0f;
    float m0 = -INFINITY, m1 = -INFINITY, l0 = 0.0f, l1 = 0.0f;

    load_tile(0, 0);
    if (NT > 1) load_tile(1, 1);

    for (int kt = 0; kt < NT; kt++) {
        if (kt + 1 < NT) { CP_WAIT1(); } else { CP_WAIT0(); }
        __syncthreads();

        const uint32_t buf = kvb + (uint32_t)(kt & 1) * ABUF;
        const uint32_t qrow = sb + (uint32_t)(wid * 16 + l16) * KSTR;

        float S[8][4];
        #pragma unroll
        for (int nt = 0; nt < 8; nt++)
            #pragma unroll
            for (int c = 0; c < 4; c++) S[nt][c] = 0.0f;

        #pragma unroll
        for (int ks = 0; ks < 4; ks++) {
            const uint32_t akoff = (uint32_t)(ks * 16 + akh * 8) * 2;
            const uint32_t koff  = (uint32_t)(ks * 16 + bkh * 8) * 2;
            uint32_t aqh[4], aql[4];
            ldsm4(aqh, qrow + akoff);           // QH region
            ldsm4(aql, qrow + QREG + akoff);    // QL region
            #pragma unroll
            for (int ng = 0; ng < 4; ng++) {
                const uint32_t row = (uint32_t)(ng * 16 + bl8 + bnh * 8) * KSTR + koff;
                uint32_t kbh[4], kbl[4];
                ldsm4(kbh, buf + 0 * REGION + row);
                ldsm4(kbl, buf + 1 * REGION + row);
                #pragma unroll
                for (int hf = 0; hf < 2; hf++) {
                    float* c = S[ng * 2 + hf];
                    const uint32_t b1[2] = { kbh[hf * 2], kbh[hf * 2 + 1] };
                    const uint32_t b2[2] = { kbl[hf * 2], kbl[hf * 2 + 1] };
                    mma_bf16(c, aqh, b1);
                    mma_bf16(c, aqh, b2);
                    mma_bf16(c, aql, b1);
                }
            }
        }

        if (kt >= 2 * qt) {
            const int qr0 = q0 + wid * 16 + g;
            #pragma unroll
            for (int nt = 0; nt < 8; nt++) {
                #pragma unroll
                for (int e = 0; e < 2; e++) {
                    const int key = kt * 64 + nt * 8 + c2 + e;
                    if (key > qr0)     S[nt][e]     = -INFINITY;
                    if (key > qr0 + 8) S[nt][2 + e] = -INFINITY;
                }
            }
        }

        float mx0 = -INFINITY, mx1 = -INFINITY;
        #pragma unroll
        for (int nt = 0; nt < 8; nt++) {
            mx0 = fmaxf(mx0, fmaxf(S[nt][0], S[nt][1]));
            mx1 = fmaxf(mx1, fmaxf(S[nt][2], S[nt][3]));
        }
        #pragma unroll
        for (int off = 1; off <= 2; off <<= 1) {
            mx0 = fmaxf(mx0, __shfl_xor_sync(0xffffffffu, mx0, off));
            mx1 = fmaxf(mx1, __shfl_xor_sync(0xffffffffu, mx1, off));
        }
        const float mn0 = fmaxf(m0, mx0);
        const float mn1 = fmaxf(m1, mx1);
        const float a0 = exp2f(m0 - mn0);
        const float a1 = exp2f(m1 - mn1);
        m0 = mn0; m1 = mn1;

        float rs0 = 0.0f, rs1 = 0.0f;
        #pragma unroll
        for (int nt = 0; nt < 8; nt++) {
            S[nt][0] = exp2f(S[nt][0] - m0);
            S[nt][1] = exp2f(S[nt][1] - m0);
            S[nt][2] = exp2f(S[nt][2] - m1);
            S[nt][3] = exp2f(S[nt][3] - m1);
            rs0 += S[nt][0] + S[nt][1];
            rs1 += S[nt][2] + S[nt][3];
        }
        #pragma unroll
        for (int off = 1; off <= 2; off <<= 1) {
            rs0 += __shfl_xor_sync(0xffffffffu, rs0, off);
            rs1 += __shfl_xor_sync(0xffffffffu, rs1, off);
        }
        l0 = l0 * a0 + rs0;
        l1 = l1 * a1 + rs1;

        #pragma unroll
        for (int nt = 0; nt < 8; nt++) {
            O[nt][0] *= a0; O[nt][1] *= a0;
            O[nt][2] *= a1; O[nt][3] *= a1;
        }

        uint32_t ph[4][4], pl[4][4];
        #pragma unroll
        for (int ks = 0; ks < 4; ks++) {
            #pragma unroll
            for (int r = 0; r < 4; r++) {
                const int nt = ks * 2 + (r >> 1);
                const float p0 = S[nt][(r & 1) * 2 + 0];
                const float p1 = S[nt][(r & 1) * 2 + 1];
                __nv_bfloat16 h0 = __float2bfloat16_rn(p0);
                __nv_bfloat16 h1 = __float2bfloat16_rn(p1);
                __nv_bfloat16 e0 = __float2bfloat16_rn(p0 - __bfloat162float(h0));
                __nv_bfloat16 e1 = __float2bfloat16_rn(p1 - __bfloat162float(h1));
                ph[ks][r] = packbf(h0, h1);
                pl[ks][r] = packbf(e0, e1);
            }
        }

        #pragma unroll
        for (int ks = 0; ks < 4; ks++) {
            const uint32_t koff = (uint32_t)(ks * 16 + bkh * 8) * 2;
            #pragma unroll
            for (int ng = 0; ng < 4; ng++) {
                const uint32_t row = (uint32_t)(ng * 16 + bl8 + bnh * 8) * KSTR + koff;
                uint32_t vbh[4], vbl[4];
                ldsm4(vbh, buf + 2 * REGION + row);
                ldsm4(vbl, buf + 3 * REGION + row);
                #pragma unroll
                for (int hf = 0; hf < 2; hf++) {
                    float* c = O[ng * 2 + hf];
                    const uint32_t b1[2] = { vbh[hf * 2], vbh[hf * 2 + 1] };
                    const uint32_t b2[2] = { vbl[hf * 2], vbl[hf * 2 + 1] };
                    mma_bf16(c, ph[ks], b1);
                    mma_bf16(c, ph[ks], b2);
                    mma_bf16(c, pl[ks], b1);
                }
            }
        }

        __syncthreads();
        if (kt + 2 < NT) load_tile(kt & 1, kt + 2);
    }

    const float inv0 = 1.0f / l0;
    const float inv1 = 1.0f / l1;
    const size_t o0 = (size_t)(b * SEQ + q0 + wid * 16 + g) * DMODEL + h * HD;
    const size_t o1 = o0 + 8 * DMODEL;
    #pragma unroll
    for (int nt = 0; nt < 8; nt++) {
        uint32_t hi, lo;
        split2(O[nt][0] * inv0, O[nt][1] * inv0, hi, lo);
        *(uint32_t*)(yh + o0 + nt * 8 + c2) = hi;
        *(uint32_t*)(yl + o0 + nt * 8 + c2) = lo;
        split2(O[nt][2] * inv1, O[nt][3] * inv1, hi, lo);
        *(uint32_t*)(yh + o1 + nt * 8 + c2) = hi;
        *(uint32_t*)(yl + o1 + nt * 8 + c2) = lo;
    }
}

// ---------------------------------------------------------------------------
// Launch
// ---------------------------------------------------------------------------
extern "C" void kernel_launch(void* const* d_in, const int* in_sizes, int n_in,
                              void* d_out, int out_size)
{
    const float* x      = (const float*)d_in[0];
    const float* W_attn = (const float*)d_in[1];
    const float* W_proj = (const float*)d_in[2];
    float* out = (float*)d_out;

    void *p_qkv, *p_xh, *p_xl, *p_yh, *p_yl, *p_wah, *p_wal, *p_wph, *p_wpl;
    void *p_qh, *p_ql, *p_kh, *p_kl, *p_vh, *p_vl;
    cudaGetSymbolAddress(&p_qkv, g_qkv);
    cudaGetSymbolAddress(&p_xh, g_xh);
    cudaGetSymbolAddress(&p_xl, g_xl);
    cudaGetSymbolAddress(&p_yh, g_yh);
    cudaGetSymbolAddress(&p_yl, g_yl);
    cudaGetSymbolAddress(&p_wah, g_wah);
    cudaGetSymbolAddress(&p_wal, g_wal);
    cudaGetSymbolAddress(&p_wph, g_wph);
    cudaGetSymbolAddress(&p_wpl, g_wpl);
    cudaGetSymbolAddress(&p_qh, g_qh);
    cudaGetSymbolAddress(&p_ql, g_ql);
    cudaGetSymbolAddress(&p_kh, g_kh);
    cudaGetSymbolAddress(&p_kl, g_kl);
    cudaGetSymbolAddress(&p_vh, g_vth);
    cudaGetSymbolAddress(&p_vl, g_vtl);
    float* qkv = (float*)p_qkv;
    __nv_bfloat16* xh = (__nv_bfloat16*)p_xh;
    __nv_bfloat16* xl = (__nv_bfloat16*)p_xl;
    __nv_bfloat16* yh = (__nv_bfloat16*)p_yh;
    __nv_bfloat16* yl = (__nv_bfloat16*)p_yl;
    __nv_bfloat16* wah = (__nv_bfloat16*)p_wah;
    __nv_bfloat16* wal = (__nv_bfloat16*)p_wal;
    __nv_bfloat16* wph = (__nv_bfloat16*)p_wph;
    __nv_bfloat16* wpl = (__nv_bfloat16*)p_wpl;
    __nv_bfloat16* qh = (__nv_bfloat16*)p_qh;
    __nv_bfloat16* ql = (__nv_bfloat16*)p_ql;
    __nv_bfloat16* kh = (__nv_bfloat16*)p_kh;
    __nv_bfloat16* kl = (__nv_bfloat16*)p_kl;
    __nv_bfloat16* vth = (__nv_bfloat16*)p_vh;
    __nv_bfloat16* vtl = (__nv_bfloat16*)p_vl;

    cudaFuncSetAttribute(tc_gemm_bf16,
                         cudaFuncAttributeMaxDynamicSharedMemorySize, SMEM_DYN);
    cudaFuncSetAttribute(attn_mma_kernel,
                         cudaFuncAttributeMaxDynamicSharedMemorySize, ATT_SMEM);

    // 0) prepasses
    split_kernel<<<(NTOK * DMODEL / 4) / 256, 256>>>(x, xh, xl);
    {
        dim3 blk(32, 8);
        transpose_split_kernel<<<dim3(QKVROW / 32, DMODEL / 32), blk>>>(
            W_attn, wah, wal, DMODEL, QKVROW);
        transpose_split_kernel<<<dim3(DMODEL / 32, DMODEL / 32), blk>>>(
            W_proj, wph, wpl, DMODEL, DMODEL);
    }

    // 1) qkv = x @ W_attn (mode 1: Q/K split written directly, V fp32)
    {
        dim3 grid(QKVROW / 128, NTOK / 128);
        tc_gemm_bf16<<<grid, 256, SMEM_DYN>>>(xh, xl, wah, wal, qkv,
                                              NTOK, QKVROW, DMODEL, 1,
                                              qh, ql, kh, kl);
    }

    // 2) split+transpose V
    {
        dim3 blk(32, 8);
        v_split_T_kernel<<<dim3(SEQ / 32, HD / 32, BATCH * NHEAD), blk>>>(qkv, vth, vtl);
    }

    // 3) attention -> y (bf16 hi/lo)
    {
        dim3 grid(SEQ / 128, NHEAD, BATCH);
        attn_mma_kernel<<<grid, 256, ATT_SMEM>>>(qh, ql, kh, kl, vth, vtl, yh, yl);
    }

    // 4) out = y @ W_proj (mode 0: plain fp32)
    {
        dim3 grid(DMODEL / 128, NTOK / 128);
        tc_gemm_bf16<<<grid, 256, SMEM_DYN>>>(yh, yl, wph, wpl, out,
                                              NTOK, DMODEL, DMODEL, 0,
                                              nullptr, nullptr, nullptr, nullptr);
    }
}